// round 8
// baseline (speedup 1.0000x reference)
#include <cuda_runtime.h>
#include <cstdint>
#include <math.h>

#define B_ROWS   16384
#define DATA_DIM 4096
#define Z_DIM    512
#define H_DIM    400
#define H_PAD    448
#define N1_PAD   512
#define QMAX     32256.0f    // 126*256: keeps hi-split in [-126,126]

typedef int8_t s8;

// ---------------- scratch (allocation-free device globals, zero-init) ------
__device__ alignas(256) s8 g_xqh [B_ROWS * DATA_DIM], g_xql [B_ROWS * DATA_DIM];
__device__ alignas(256) s8 g_h1qh[B_ROWS * H_PAD],    g_h1ql[B_ROWS * H_PAD];
__device__ alignas(256) s8 g_zqh [B_ROWS * Z_DIM],    g_zql [B_ROWS * Z_DIM];
__device__ alignas(256) s8 g_h3qh[B_ROWS * H_PAD],    g_h3ql[B_ROWS * H_PAD];
__device__ alignas(256) float g_h1f[B_ROWS * H_PAD];   // pad cols stay zero
__device__ alignas(256) float g_h3f[B_ROWS * H_PAD];
__device__ float g_sx[B_ROWS], g_sh1[B_ROWS], g_sz[B_ROWS], g_sh3[B_ROWS];
__device__ unsigned g_rm1[B_ROWS], g_rm3[B_ROWS];     // rowmax (fp32 bits)
__device__ float g_std[B_ROWS];
// quantized transposed weights [Npad][Kpad] s8 hi/lo + per-col scales
__device__ alignas(256) s8 g_W1qh [N1_PAD * DATA_DIM], g_W1ql [N1_PAD * DATA_DIM];
__device__ alignas(256) s8 g_W21qh[Z_DIM * H_PAD],     g_W21ql[Z_DIM * H_PAD];
__device__ alignas(256) s8 g_W3qh [N1_PAD * Z_DIM],    g_W3ql [N1_PAD * Z_DIM];
__device__ alignas(256) s8 g_W4qh [DATA_DIM * H_PAD],  g_W4ql [DATA_DIM * H_PAD];
__device__ float g_sW1[N1_PAD], g_iW1[N1_PAD];
__device__ float g_sW21[Z_DIM], g_iW21[Z_DIM];
__device__ float g_sW3[N1_PAD], g_iW3[N1_PAD];
__device__ float g_sW4[DATA_DIM], g_iW4[DATA_DIM];

// ---------------- PTX helpers ----------------------------------------------
__device__ __forceinline__ uint32_t smem_u32(const void* p) {
    uint32_t a;
    asm("{ .reg .u64 t; cvta.to.shared.u64 t, %1; cvt.u32.u64 %0, t; }"
        : "=r"(a) : "l"(p));
    return a;
}
__device__ __forceinline__ void cp16(uint32_t dst, const void* src) {
    asm volatile("cp.async.cg.shared.global [%0], [%1], 16;"
                 :: "r"(dst), "l"(src) : "memory");
}
__device__ __forceinline__ void cp_commit() {
    asm volatile("cp.async.commit_group;" ::: "memory");
}
template <int N> __device__ __forceinline__ void cp_wait() {
    asm volatile("cp.async.wait_group %0;" :: "n"(N) : "memory");
}
#define LDSM4(R, addr) \
    asm volatile("ldmatrix.sync.aligned.m8n8.x4.shared.b16 {%0,%1,%2,%3}, [%4];" \
                 : "=r"((R)[0]), "=r"((R)[1]), "=r"((R)[2]), "=r"((R)[3])      \
                 : "r"(addr))
#define IMMA(C, A, B0, B1) \
    asm volatile("mma.sync.aligned.m16n8k32.row.col.s32.s8.s8.s32 "            \
                 "{%0,%1,%2,%3}, {%4,%5,%6,%7}, {%8,%9}, {%0,%1,%2,%3};"       \
                 : "+r"((C)[0]), "+r"((C)[1]), "+r"((C)[2]), "+r"((C)[3])      \
                 : "r"((A)[0]), "r"((A)[1]), "r"((A)[2]), "r"((A)[3]),         \
                   "r"(B0), "r"(B1))

// int16 quantize + hi/lo int8 split (exact: v16 = hi*256 + lo)
__device__ __forceinline__ void qsplit(float v, float inv, s8& h, s8& l) {
    const int v16 = __float2int_rn(v * inv);
    const int ih  = (v16 + 128) >> 8;
    h = (s8)ih;
    l = (s8)(v16 - (ih << 8));
}

// smem stage: 4 matrices [128 rows][64 s8 + 16 pad] (80 B rows)
#define ROWB     80
#define MAT_SZ   (128 * ROWB)          // 10240
#define STAGE_SZ (4 * MAT_SZ)          // 40960
#define OFF_AH   0
#define OFF_AL   MAT_SZ
#define OFF_BH   (2 * MAT_SZ)
#define OFF_BL   (3 * MAT_SZ)
#define SMEM_TOT (3 * STAGE_SZ)        // 122880, 3-stage pipeline

// ---------------- stage loader: K-chunk 64 s8, cp.async 16B ---------------
__device__ __forceinline__ void ld_stage(
    uint32_t s0, int tid,
    const s8* __restrict__ Ah, const s8* __restrict__ Al, size_t arow0, int lda,
    const s8* __restrict__ Bh, const s8* __restrict__ Bl, size_t brow0, int ldb,
    int k0)
{
#pragma unroll
    for (int j = 0; j < 8; j++) {
        const int idx = tid + j * 256;          // 0..2047
        const int mat = idx >> 9;               // 0:Ah 1:Al 2:Bh 3:Bl
        const int rem = idx & 511;
        const int row = rem >> 2;               // 0..127
        const int ch  = rem & 3;                // 16B chunk
        const s8* src;
        if (mat == 0)      src = Ah + (arow0 + row) * (size_t)lda + k0 + ch * 16;
        else if (mat == 1) src = Al + (arow0 + row) * (size_t)lda + k0 + ch * 16;
        else if (mat == 2) src = Bh + (brow0 + row) * (size_t)ldb + k0 + ch * 16;
        else               src = Bl + (brow0 + row) * (size_t)ldb + k0 + ch * 16;
        cp16(s0 + mat * MAT_SZ + row * ROWB + ch * 16, src);
    }
}

// ---------------- split-int8 tensor-core GEMM ------------------------------
// C[128*by.., 128*bx..] = epi((A16 @ B16^T) * sA[row]*sB[col] + bias)
// A: s8 hi/lo [M][lda]; B: s8 hi/lo [Npad][ldb] K-major.
// EPI: 0 none, 1 relu, 2 sigmoid.  MAXOUT: atomicMax row abs-max into rmax.
template <int EPI, int MAXOUT>
__global__ __launch_bounds__(256) void gemm_i8(
    const s8* __restrict__ Ah, const s8* __restrict__ Al, int lda,
    const s8* __restrict__ Bh, const s8* __restrict__ Bl, int ldb,
    const float* __restrict__ sA, const float* __restrict__ sB,
    const float* __restrict__ bias, float* __restrict__ C, int ldc,
    int nout, int K, unsigned* __restrict__ rmax)
{
    extern __shared__ char smem[];
    const uint32_t sb = smem_u32(smem);
    const int tid  = threadIdx.x;
    const int wid  = tid >> 5, lane = tid & 31;
    const int wm   = wid & 1,  wn   = wid >> 1;   // 2 M-warps x 4 N-warps
    const int bx   = blockIdx.x, by = blockIdx.y;
    const size_t arow0 = (size_t)by * 128;
    const size_t brow0 = (size_t)bx * 128;

    int hh[4][4][4], md[4][4][4];
#pragma unroll
    for (int a = 0; a < 4; a++)
#pragma unroll
        for (int b = 0; b < 4; b++)
#pragma unroll
            for (int c = 0; c < 4; c++) { hh[a][b][c] = 0; md[a][b][c] = 0; }

    const int NC = K >> 6;                        // 64-wide s8 K chunks
    ld_stage(sb, tid, Ah, Al, arow0, lda, Bh, Bl, brow0, ldb, 0);
    cp_commit();
    if (NC > 1) {
        ld_stage(sb + STAGE_SZ, tid, Ah, Al, arow0, lda, Bh, Bl, brow0, ldb, 64);
        cp_commit();
    }

    for (int i = 0; i < NC; i++) {
        if (i + 2 < NC) {
            ld_stage(sb + ((i + 2) % 3) * STAGE_SZ, tid,
                     Ah, Al, arow0, lda, Bh, Bl, brow0, ldb, (i + 2) << 6);
            cp_commit();
            cp_wait<2>();
        } else if (i + 1 < NC) {
            cp_wait<1>();
        } else {
            cp_wait<0>();
        }
        __syncthreads();

        const uint32_t st = sb + (i % 3) * STAGE_SZ;
#pragma unroll
        for (int ks = 0; ks < 2; ks++) {          // two k32 steps
            uint32_t ah[4][4], al[4][4], bh[4][2], bl[4][2];
#pragma unroll
            for (int mt = 0; mt < 4; mt++) {
                const int row = wm * 64 + mt * 16 + (lane & 15);
                const uint32_t aoff = row * ROWB + ks * 32 + ((lane >> 4) << 4);
                LDSM4(ah[mt], st + OFF_AH + aoff);
                LDSM4(al[mt], st + OFF_AL + aoff);
            }
#pragma unroll
            for (int nt = 0; nt < 2; nt++) {
                const int row = wn * 32 + nt * 16 + (lane & 7) + ((lane >> 4) << 3);
                const uint32_t boff = row * ROWB + ks * 32 + ((lane >> 3) & 1) * 16;
                uint32_t r[4];
                LDSM4(r, st + OFF_BH + boff);
                bh[nt * 2][0] = r[0]; bh[nt * 2][1] = r[1];
                bh[nt * 2 + 1][0] = r[2]; bh[nt * 2 + 1][1] = r[3];
                LDSM4(r, st + OFF_BL + boff);
                bl[nt * 2][0] = r[0]; bl[nt * 2][1] = r[1];
                bl[nt * 2 + 1][0] = r[2]; bl[nt * 2 + 1][1] = r[3];
            }
#pragma unroll
            for (int mt = 0; mt < 4; mt++)
#pragma unroll
                for (int n = 0; n < 4; n++) {
                    IMMA(hh[mt][n], ah[mt], bh[n][0], bh[n][1]);
                    IMMA(md[mt][n], ah[mt], bl[n][0], bl[n][1]);
                    IMMA(md[mt][n], al[mt], bh[n][0], bh[n][1]);
                }
        }
        __syncthreads();
    }

    // ---- epilogue: dequant + bias + activation (+ optional rowmax) ----
#pragma unroll
    for (int mt = 0; mt < 4; mt++) {
        const size_t r0 = arow0 + wm * 64 + mt * 16 + (lane >> 2);
        const float sa0 = sA[r0], sa1 = sA[r0 + 8];
        float m0 = 0.0f, m1 = 0.0f;
#pragma unroll
        for (int n8 = 0; n8 < 4; n8++) {
            const int gc = bx * 128 + wn * 32 + n8 * 8 + (lane & 3) * 2;
            if (gc >= nout) continue;
            const float sb0 = sB[gc], sb1 = sB[gc + 1];
            const float bi0 = bias[gc], bi1 = bias[gc + 1];
            float v[4];
            v[0] = fmaf(sa0 * sb0, fmaf(65536.0f, (float)hh[mt][n8][0], 256.0f * (float)md[mt][n8][0]), bi0);
            v[1] = fmaf(sa0 * sb1, fmaf(65536.0f, (float)hh[mt][n8][1], 256.0f * (float)md[mt][n8][1]), bi1);
            v[2] = fmaf(sa1 * sb0, fmaf(65536.0f, (float)hh[mt][n8][2], 256.0f * (float)md[mt][n8][2]), bi0);
            v[3] = fmaf(sa1 * sb1, fmaf(65536.0f, (float)hh[mt][n8][3], 256.0f * (float)md[mt][n8][3]), bi1);
#pragma unroll
            for (int q = 0; q < 4; q++) {
                if (EPI == 1) v[q] = fmaxf(v[q], 0.0f);
                if (EPI == 2) v[q] = 1.0f / (1.0f + __expf(-v[q]));
            }
            float2 p0, p1;
            p0.x = v[0]; p0.y = v[1];  p1.x = v[2]; p1.y = v[3];
            *reinterpret_cast<float2*>(C + r0 * ldc + gc)       = p0;
            *reinterpret_cast<float2*>(C + (r0 + 8) * ldc + gc) = p1;
            if (MAXOUT) {
                m0 = fmaxf(m0, fmaxf(fabsf(v[0]), fabsf(v[1])));
                m1 = fmaxf(m1, fmaxf(fabsf(v[2]), fabsf(v[3])));
            }
        }
        if (MAXOUT) {
            atomicMax(&rmax[r0],     __float_as_uint(m0));
            atomicMax(&rmax[r0 + 8], __float_as_uint(m1));
        }
    }
}

// ---------------- x -> per-row int16 quant + split --------------------------
__global__ __launch_bounds__(512) void quant_x(
    const float* __restrict__ x, s8* __restrict__ qh, s8* __restrict__ ql)
{
    __shared__ float red[16];
    const int row = blockIdx.x, t = threadIdx.x;
    const size_t base = (size_t)row * DATA_DIM + t * 8;
    const float4 a = *reinterpret_cast<const float4*>(x + base);
    const float4 b = *reinterpret_cast<const float4*>(x + base + 4);
    float m = fmaxf(fmaxf(fmaxf(fabsf(a.x), fabsf(a.y)), fmaxf(fabsf(a.z), fabsf(a.w))),
                    fmaxf(fmaxf(fabsf(b.x), fabsf(b.y)), fmaxf(fabsf(b.z), fabsf(b.w))));
#pragma unroll
    for (int o = 16; o > 0; o >>= 1) m = fmaxf(m, __shfl_xor_sync(~0u, m, o));
    if ((t & 31) == 0) red[t >> 5] = m;
    __syncthreads();
    if (t < 16) {
        float w = red[t];
#pragma unroll
        for (int o = 8; o > 0; o >>= 1) w = fmaxf(w, __shfl_xor_sync(0xffffu, w, o));
        if (t == 0) red[0] = w;
    }
    __syncthreads();
    const float rm  = red[0];
    const float inv = rm > 0.f ? QMAX / rm : 0.f;
    if (t == 0) g_sx[row] = rm / QMAX;

    union { s8 b[8]; uint2 u; } H, L;
    const float vv[8] = {a.x, a.y, a.z, a.w, b.x, b.y, b.z, b.w};
#pragma unroll
    for (int q = 0; q < 8; q++) qsplit(vv[q], inv, H.b[q], L.b[q]);
    *reinterpret_cast<uint2*>(qh + base) = H.u;
    *reinterpret_cast<uint2*>(ql + base) = L.u;
}

// ---------------- weight column abs-max (per output neuron) ----------------
__global__ void wcolmax(const float* __restrict__ W1, const float* __restrict__ W21,
                        const float* __restrict__ W3, const float* __restrict__ W4)
{
    const int b = blockIdx.x, t = threadIdx.x;
    const float* W; int K, N; float *S, *I; int col0;
    if (b < 2)       { W = W1;  K = DATA_DIM; N = H_DIM;    S = g_sW1;  I = g_iW1;  col0 = b * 256; }
    else if (b < 4)  { W = W21; K = H_DIM;    N = Z_DIM;    S = g_sW21; I = g_iW21; col0 = (b - 2) * 256; }
    else if (b < 6)  { W = W3;  K = Z_DIM;    N = H_DIM;    S = g_sW3;  I = g_iW3;  col0 = (b - 4) * 256; }
    else             { W = W4;  K = H_DIM;    N = DATA_DIM; S = g_sW4;  I = g_iW4;  col0 = (b - 6) * 256; }
    const int col = col0 + t;
    if (col >= N) return;
    float m = 0.f;
    for (int k = 0; k < K; k++) m = fmaxf(m, fabsf(W[(size_t)k * N + col]));
    S[col] = m / QMAX;
    I[col] = m > 0.f ? QMAX / m : 0.f;
}

// ---------------- weight prep: transpose + quantize + split ----------------
__global__ void prep_q(const float* __restrict__ W, int K, int N,
                       const float* __restrict__ inv,
                       s8* __restrict__ Qh, s8* __restrict__ Ql, int Kp, int Np)
{
    __shared__ float tbuf[32][33];
    const int k0 = blockIdx.x * 32, n0 = blockIdx.y * 32;
    const int tx = threadIdx.x, ty = threadIdx.y;     // (32, 8)
#pragma unroll
    for (int j = 0; j < 4; j++) {
        const int k = k0 + ty + j * 8, n = n0 + tx;
        tbuf[ty + j * 8][tx] = (k < K && n < N) ? W[(size_t)k * N + n] : 0.0f;
    }
    __syncthreads();
#pragma unroll
    for (int j = 0; j < 4; j++) {
        const int n = n0 + ty + j * 8, k = k0 + tx;
        if (n < Np && k < Kp) {
            s8 h, l;
            qsplit(tbuf[tx][ty + j * 8], inv[n], h, l);
            Qh[(size_t)n * Kp + k] = h;
            Ql[(size_t)n * Kp + k] = l;
        }
    }
}

// ---------------- requantize h (fp32 + rowmax -> int8 hi/lo) ---------------
__global__ void quant_h(const float* __restrict__ hf, const unsigned* __restrict__ rm,
                        s8* __restrict__ qh, s8* __restrict__ ql,
                        float* __restrict__ srow)
{
    const int row = blockIdx.x, t = threadIdx.x;     // 448 threads
    const float rmax = __uint_as_float(rm[row]);
    const float inv  = rmax > 0.f ? QMAX / rmax : 0.f;
    s8 h, l;
    qsplit(hf[(size_t)row * H_PAD + t], inv, h, l);
    qh[(size_t)row * H_PAD + t] = h;
    ql[(size_t)row * H_PAD + t] = l;
    if (t == 0) srow[row] = rmax / QMAX;
}

// ------------- per-row heads: rho = tanh(h1@W22+b22), logs = h1@W23+b23 ----
__global__ void rho_logs_kernel(const float* __restrict__ h1f,
                                const float* __restrict__ W22,
                                const float* __restrict__ b22,
                                const float* __restrict__ W23,
                                const float* __restrict__ b23,
                                float* __restrict__ rho_out,
                                float* __restrict__ logs_out)
{
    const int row  = blockIdx.x * blockDim.y + threadIdx.y;
    const int lane = threadIdx.x;
    const float* hr = h1f + (size_t)row * H_PAD;
    float a = 0.f, b = 0.f;
    for (int i = lane; i < H_DIM; i += 32) {
        const float h = hr[i];
        a = fmaf(h, W22[i], a);
        b = fmaf(h, W23[i], b);
    }
#pragma unroll
    for (int o = 16; o > 0; o >>= 1) {
        a += __shfl_xor_sync(0xffffffffu, a, o);
        b += __shfl_xor_sync(0xffffffffu, b, o);
    }
    if (lane == 0) {
        const float logs = b + b23[0];
        rho_out[row]  = tanhf(a + b22[0]);
        logs_out[row] = logs;
        g_std[row]    = sqrtf(expf(logs));
    }
}

// ------------- z = cumsum(eps*std)+mu, quantized in-warp -------------------
__global__ __launch_bounds__(256) void scan_kernel(
    const float* __restrict__ eps, const float* __restrict__ mu,
    s8* __restrict__ zqh, s8* __restrict__ zql)
{
    const int warp = threadIdx.x >> 5, lane = threadIdx.x & 31;
    const int row  = blockIdx.x * 8 + warp;
    const float s  = g_std[row];
    const size_t base = (size_t)row * Z_DIM + lane * 16;

    float v[16];
#pragma unroll
    for (int q = 0; q < 4; q++) {
        const float4 e = *reinterpret_cast<const float4*>(eps + base + q * 4);
        v[q * 4 + 0] = e.x * s;  v[q * 4 + 1] = e.y * s;
        v[q * 4 + 2] = e.z * s;  v[q * 4 + 3] = e.w * s;
    }
#pragma unroll
    for (int q = 1; q < 16; q++) v[q] += v[q - 1];
    float tot = v[15];
#pragma unroll
    for (int o = 1; o < 32; o <<= 1) {
        const float n = __shfl_up_sync(0xffffffffu, tot, o);
        if (lane >= o) tot += n;
    }
    const float off = tot - v[15];

    float m = 0.f;
#pragma unroll
    for (int q = 0; q < 4; q++) {
        const float4 mm = *reinterpret_cast<const float4*>(mu + base + q * 4);
        v[q * 4 + 0] += off + mm.x;  v[q * 4 + 1] += off + mm.y;
        v[q * 4 + 2] += off + mm.z;  v[q * 4 + 3] += off + mm.w;
    }
#pragma unroll
    for (int q = 0; q < 16; q++) m = fmaxf(m, fabsf(v[q]));
#pragma unroll
    for (int o = 16; o > 0; o >>= 1) m = fmaxf(m, __shfl_xor_sync(~0u, m, o));
    const float inv = m > 0.f ? QMAX / m : 0.f;
    if (lane == 0) g_sz[row] = m / QMAX;

    union { s8 b[16]; uint4 u; } H, L;
#pragma unroll
    for (int q = 0; q < 16; q++) qsplit(v[q], inv, H.b[q], L.b[q]);
    *reinterpret_cast<uint4*>(zqh + base) = H.u;
    *reinterpret_cast<uint4*>(zql + base) = L.u;
}

// ---------------------------------------------------------------------------
extern "C" void kernel_launch(void* const* d_in, const int* in_sizes, int n_in,
                              void* d_out, int out_size)
{
    const float* x   = (const float*)d_in[0];
    const float* eps = (const float*)d_in[1];
    const float* W1  = (const float*)d_in[2];
    const float* b1  = (const float*)d_in[3];
    const float* W21 = (const float*)d_in[4];
    const float* b21 = (const float*)d_in[5];
    const float* W22 = (const float*)d_in[6];
    const float* b22 = (const float*)d_in[7];
    const float* W23 = (const float*)d_in[8];
    const float* b23 = (const float*)d_in[9];
    const float* W3  = (const float*)d_in[10];
    const float* b3  = (const float*)d_in[11];
    const float* W4  = (const float*)d_in[12];
    const float* b4  = (const float*)d_in[13];

    float* out       = (float*)d_out;
    float* out_recon = out;                                    // [B, 4096]
    float* out_mu    = out_recon + (size_t)B_ROWS * DATA_DIM;  // [B, 512]
    float* out_rho   = out_mu    + (size_t)B_ROWS * Z_DIM;     // [B, 1]
    float* out_logs  = out_rho   + B_ROWS;                     // [B, 1]

    s8 *xqh, *xql, *h1qh, *h1ql, *zqh, *zql, *h3qh, *h3ql;
    s8 *W1qh, *W1ql, *W21qh, *W21ql, *W3qh, *W3ql, *W4qh, *W4ql;
    float *h1f, *h3f, *sx, *sh1, *sz, *sh3;
    float *sW1, *iW1, *sW21, *iW21, *sW3, *iW3, *sW4, *iW4;
    unsigned *rm1, *rm3;
    cudaGetSymbolAddress((void**)&xqh,  g_xqh);   cudaGetSymbolAddress((void**)&xql,  g_xql);
    cudaGetSymbolAddress((void**)&h1qh, g_h1qh);  cudaGetSymbolAddress((void**)&h1ql, g_h1ql);
    cudaGetSymbolAddress((void**)&zqh,  g_zqh);   cudaGetSymbolAddress((void**)&zql,  g_zql);
    cudaGetSymbolAddress((void**)&h3qh, g_h3qh);  cudaGetSymbolAddress((void**)&h3ql, g_h3ql);
    cudaGetSymbolAddress((void**)&h1f,  g_h1f);   cudaGetSymbolAddress((void**)&h3f,  g_h3f);
    cudaGetSymbolAddress((void**)&sx,   g_sx);    cudaGetSymbolAddress((void**)&sh1,  g_sh1);
    cudaGetSymbolAddress((void**)&sz,   g_sz);    cudaGetSymbolAddress((void**)&sh3,  g_sh3);
    cudaGetSymbolAddress((void**)&rm1,  g_rm1);   cudaGetSymbolAddress((void**)&rm3,  g_rm3);
    cudaGetSymbolAddress((void**)&W1qh, g_W1qh);  cudaGetSymbolAddress((void**)&W1ql, g_W1ql);
    cudaGetSymbolAddress((void**)&W21qh,g_W21qh); cudaGetSymbolAddress((void**)&W21ql,g_W21ql);
    cudaGetSymbolAddress((void**)&W3qh, g_W3qh);  cudaGetSymbolAddress((void**)&W3ql, g_W3ql);
    cudaGetSymbolAddress((void**)&W4qh, g_W4qh);  cudaGetSymbolAddress((void**)&W4ql, g_W4ql);
    cudaGetSymbolAddress((void**)&sW1,  g_sW1);   cudaGetSymbolAddress((void**)&iW1,  g_iW1);
    cudaGetSymbolAddress((void**)&sW21, g_sW21);  cudaGetSymbolAddress((void**)&iW21, g_iW21);
    cudaGetSymbolAddress((void**)&sW3,  g_sW3);   cudaGetSymbolAddress((void**)&iW3,  g_iW3);
    cudaGetSymbolAddress((void**)&sW4,  g_sW4);   cudaGetSymbolAddress((void**)&iW4,  g_iW4);

    cudaFuncSetAttribute(gemm_i8<1, 1>, cudaFuncAttributeMaxDynamicSharedMemorySize, SMEM_TOT);
    cudaFuncSetAttribute(gemm_i8<0, 0>, cudaFuncAttributeMaxDynamicSharedMemorySize, SMEM_TOT);
    cudaFuncSetAttribute(gemm_i8<2, 0>, cudaFuncAttributeMaxDynamicSharedMemorySize, SMEM_TOT);

    const dim3 pb(32, 8);

    // idx0: x quantize; idx1: weight col maxes; idx2: W1 prep
    quant_x<<<B_ROWS, 512>>>(x, xqh, xql);
    wcolmax<<<22, 256>>>(W1, W21, W3, W4);
    prep_q<<<dim3(DATA_DIM / 32, N1_PAD / 32), pb>>>(W1, DATA_DIM, H_DIM, iW1, W1qh, W1ql, DATA_DIM, N1_PAD);

    // idx3 (ncu slot): h1 = relu(x @ W1 + b1) -> fp32 + rowmax
    gemm_i8<1, 1><<<dim3(N1_PAD / 128, B_ROWS / 128), 256, SMEM_TOT>>>(
        xqh, xql, DATA_DIM, W1qh, W1ql, DATA_DIM, sx, sW1, b1,
        h1f, H_PAD, H_DIM, DATA_DIM, rm1);

    // idx4: rho / logs / std (fp32 h1)
    rho_logs_kernel<<<B_ROWS / 8, dim3(32, 8)>>>(
        h1f, W22, b22, W23, b23, out_rho, out_logs);

    // idx5: quantize h1; idx6: W21 prep
    quant_h<<<B_ROWS, H_PAD>>>(h1f, rm1, h1qh, h1ql, sh1);
    prep_q<<<dim3(H_PAD / 32, Z_DIM / 32), pb>>>(W21, H_DIM, Z_DIM, iW21, W21qh, W21ql, H_PAD, Z_DIM);

    // idx7: mu = h1 @ W21 + b21 -> fp32 output
    gemm_i8<0, 0><<<dim3(Z_DIM / 128, B_ROWS / 128), 256, SMEM_TOT>>>(
        h1qh, h1ql, H_PAD, W21qh, W21ql, H_PAD, sh1, sW21, b21,
        out_mu, Z_DIM, Z_DIM, H_PAD, nullptr);

    // idx8: z = cumsum(eps*std)+mu -> quantized
    scan_kernel<<<B_ROWS / 8, 256>>>(eps, out_mu, zqh, zql);

    // idx9: W3 prep; idx10: h3 = relu(z @ W3 + b3) -> fp32 + rowmax
    prep_q<<<dim3(Z_DIM / 32, N1_PAD / 32), pb>>>(W3, Z_DIM, H_DIM, iW3, W3qh, W3ql, Z_DIM, N1_PAD);
    gemm_i8<1, 1><<<dim3(N1_PAD / 128, B_ROWS / 128), 256, SMEM_TOT>>>(
        zqh, zql, Z_DIM, W3qh, W3ql, Z_DIM, sz, sW3, b3,
        h3f, H_PAD, H_DIM, Z_DIM, rm3);

    // idx11: quantize h3; idx12: W4 prep
    quant_h<<<B_ROWS, H_PAD>>>(h3f, rm3, h3qh, h3ql, sh3);
    prep_q<<<dim3(H_PAD / 32, DATA_DIM / 32), pb>>>(W4, H_DIM, DATA_DIM, iW4, W4qh, W4ql, H_PAD, DATA_DIM);

    // idx13: recon = sigmoid(h3 @ W4 + b4) -> fp32 output
    gemm_i8<2, 0><<<dim3(DATA_DIM / 128, B_ROWS / 128), 256, SMEM_TOT>>>(
        h3qh, h3ql, H_PAD, W4qh, W4ql, H_PAD, sh3, sW4, b4,
        out_recon, DATA_DIM, DATA_DIM, H_PAD, nullptr);
}

// round 9
// speedup vs baseline: 2.7888x; 2.7888x over previous
#include <cuda_runtime.h>
#include <cuda_bf16.h>
#include <cstdint>
#include <math.h>

#define B_ROWS   16384
#define DATA_DIM 4096
#define Z_DIM    512
#define H_DIM    400
#define H_PAD    448     // H padded to multiple of 32 (K use)
#define N1_PAD   512     // H padded to multiple of 128 (N-tile use)

typedef __nv_bfloat16 bf16;

// ---------------- scratch (allocation-free device globals, zero-init) ------
__device__ alignas(256) bf16 g_xh [B_ROWS * DATA_DIM];
__device__ alignas(256) bf16 g_xl [B_ROWS * DATA_DIM];
__device__ alignas(256) bf16 g_h1h[B_ROWS * H_PAD];    // pad cols stay zero
__device__ alignas(256) bf16 g_h1l[B_ROWS * H_PAD];
__device__ alignas(256) bf16 g_zh [B_ROWS * Z_DIM];
__device__ alignas(256) bf16 g_zl [B_ROWS * Z_DIM];
__device__ alignas(256) bf16 g_h3h[B_ROWS * H_PAD];
__device__ alignas(256) bf16 g_h3l[B_ROWS * H_PAD];
__device__ float g_std[B_ROWS];
// transposed + split weights [Npad][Kpad] bf16 (K-major), zero padded
__device__ alignas(256) bf16 g_W1h [N1_PAD * DATA_DIM], g_W1l [N1_PAD * DATA_DIM];
__device__ alignas(256) bf16 g_W21h[Z_DIM * H_PAD],     g_W21l[Z_DIM * H_PAD];
__device__ alignas(256) bf16 g_W3h [N1_PAD * Z_DIM],    g_W3l [N1_PAD * Z_DIM];
__device__ alignas(256) bf16 g_W4h [DATA_DIM * H_PAD],  g_W4l [DATA_DIM * H_PAD];

// ---------------- PTX helpers ----------------------------------------------
__device__ __forceinline__ uint32_t smem_u32(const void* p) {
    uint32_t a;
    asm("{ .reg .u64 t; cvta.to.shared.u64 t, %1; cvt.u32.u64 %0, t; }"
        : "=r"(a) : "l"(p));
    return a;
}
__device__ __forceinline__ void cp16(uint32_t dst, const void* src) {
    asm volatile("cp.async.cg.shared.global [%0], [%1], 16;"
                 :: "r"(dst), "l"(src) : "memory");
}
__device__ __forceinline__ void cp_commit() {
    asm volatile("cp.async.commit_group;" ::: "memory");
}
template <int N> __device__ __forceinline__ void cp_wait() {
    asm volatile("cp.async.wait_group %0;" :: "n"(N) : "memory");
}
#define LDSM4(R, addr) \
    asm volatile("ldmatrix.sync.aligned.m8n8.x4.shared.b16 {%0,%1,%2,%3}, [%4];" \
                 : "=r"((R)[0]), "=r"((R)[1]), "=r"((R)[2]), "=r"((R)[3])      \
                 : "r"(addr))
#define MMA16816(C, A, B0, B1) \
    asm volatile("mma.sync.aligned.m16n8k16.row.col.f32.bf16.bf16.f32 "        \
                 "{%0,%1,%2,%3}, {%4,%5,%6,%7}, {%8,%9}, {%0,%1,%2,%3};"       \
                 : "+f"((C)[0]), "+f"((C)[1]), "+f"((C)[2]), "+f"((C)[3])      \
                 : "r"((A)[0]), "r"((A)[1]), "r"((A)[2]), "r"((A)[3]),         \
                   "r"(B0), "r"(B1))

// smem stage: 4 matrices [128 rows][32 bf16 + 8 pad] (80 B rows, 16B aligned)
#define ROWB     80
#define MAT_SZ   10240                 // 128*80
#define OFF_AH   0
#define OFF_AL   10240
#define OFF_BH   20480
#define OFF_BL   30720
#define STAGE_SZ 40960
#define SMEM_TOT (2 * STAGE_SZ)       // 81920 -> two CTAs per SM

// ---------------- stage loader: K-chunk 32, cp.async 16B ------------------
__device__ __forceinline__ void ld_stage(
    uint32_t s0, int tid,
    const bf16* __restrict__ Ah, const bf16* __restrict__ Al,
    size_t arow0, int lda,
    const bf16* __restrict__ Bh, const bf16* __restrict__ Bl,
    size_t brow0, int ldb, int k0)
{
#pragma unroll
    for (int j = 0; j < 8; j++) {
        const int idx = tid + j * 256;          // 0..2047
        const int mat = idx >> 9;               // 0:Ah 1:Al 2:Bh 3:Bl
        const int rem = idx & 511;
        const int row = rem >> 2;               // 0..127
        const int ch  = rem & 3;                // 16B chunk (8 bf16)
        const bf16* src;
        if (mat == 0)      src = Ah + (arow0 + row) * (size_t)lda + k0 + ch * 8;
        else if (mat == 1) src = Al + (arow0 + row) * (size_t)lda + k0 + ch * 8;
        else if (mat == 2) src = Bh + (brow0 + row) * (size_t)ldb + k0 + ch * 8;
        else               src = Bl + (brow0 + row) * (size_t)ldb + k0 + ch * 8;
        cp16(s0 + mat * MAT_SZ + row * ROWB + ch * 16, src);
    }
}

// ---------------- split-bf16 tensor-core GEMM ------------------------------
// C[128*by.., 128*bx..] = epi(A @ B^T + bias)
// A: bf16 hi/lo [M][lda] row-major; B: bf16 hi/lo [Npad][ldb] K-major.
// EPI: 0 none, 1 relu, 2 sigmoid.  SPLIT: 1 -> store hi/lo bf16, 0 -> fp32.
template <int EPI, int SPLIT>
__global__ __launch_bounds__(256, 2) void gemm_mma(
    const bf16* __restrict__ Ah, const bf16* __restrict__ Al, int lda,
    const bf16* __restrict__ Bh, const bf16* __restrict__ Bl, int ldb,
    const float* __restrict__ bias,
    float* __restrict__ Cf, bf16* __restrict__ Ch, bf16* __restrict__ Cl,
    int ldc, int nout, int K)
{
    extern __shared__ char smem[];
    const uint32_t sb = smem_u32(smem);
    const int tid  = threadIdx.x;
    const int wid  = tid >> 5, lane = tid & 31;
    const int wm   = wid & 1,  wn   = wid >> 1;   // 2 M-warps x 4 N-warps
    const int bx   = blockIdx.x, by = blockIdx.y;
    const size_t arow0 = (size_t)by * 128;
    const size_t brow0 = (size_t)bx * 128;

    float acc[4][4][4];
#pragma unroll
    for (int a = 0; a < 4; a++)
#pragma unroll
        for (int b = 0; b < 4; b++)
#pragma unroll
            for (int c = 0; c < 4; c++) acc[a][b][c] = 0.0f;

    const int NC = K >> 5;                        // 32-wide K chunks
    ld_stage(sb, tid, Ah, Al, arow0, lda, Bh, Bl, brow0, ldb, 0);
    cp_commit();

    for (int i = 0; i < NC; i++) {
        if (i + 1 < NC) {
            ld_stage(sb + ((i + 1) & 1) * STAGE_SZ, tid,
                     Ah, Al, arow0, lda, Bh, Bl, brow0, ldb, (i + 1) << 5);
            cp_commit();
            cp_wait<1>();
        } else {
            cp_wait<0>();
        }
        __syncthreads();

        const uint32_t st = sb + (i & 1) * STAGE_SZ;
#pragma unroll
        for (int ks = 0; ks < 2; ks++) {
            uint32_t ah[4][4], al[4][4], bh[4][2], bl[4][2];
#pragma unroll
            for (int mt = 0; mt < 4; mt++) {
                const int row = wm * 64 + mt * 16 + (lane & 15);
                const uint32_t aoff = row * ROWB + ks * 32 + ((lane >> 4) << 4);
                LDSM4(ah[mt], st + OFF_AH + aoff);
                LDSM4(al[mt], st + OFF_AL + aoff);
            }
#pragma unroll
            for (int nt = 0; nt < 2; nt++) {
                const int row = wn * 32 + nt * 16 + (lane & 7) + ((lane >> 4) << 3);
                const uint32_t boff = row * ROWB + ks * 32 + ((lane >> 3) & 1) * 16;
                uint32_t r[4];
                LDSM4(r, st + OFF_BH + boff);
                bh[nt * 2][0] = r[0]; bh[nt * 2][1] = r[1];
                bh[nt * 2 + 1][0] = r[2]; bh[nt * 2 + 1][1] = r[3];
                LDSM4(r, st + OFF_BL + boff);
                bl[nt * 2][0] = r[0]; bl[nt * 2][1] = r[1];
                bl[nt * 2 + 1][0] = r[2]; bl[nt * 2 + 1][1] = r[3];
            }
#pragma unroll
            for (int mt = 0; mt < 4; mt++)
#pragma unroll
                for (int n = 0; n < 4; n++) {
                    MMA16816(acc[mt][n], ah[mt], bh[n][0], bh[n][1]);
                    MMA16816(acc[mt][n], al[mt], bh[n][0], bh[n][1]);
                    MMA16816(acc[mt][n], ah[mt], bl[n][0], bl[n][1]);
                }
        }
        __syncthreads();
    }

    // ---- epilogue: bias + activation, direct register stores ----
#pragma unroll
    for (int n8 = 0; n8 < 4; n8++) {
        const int gc = bx * 128 + wn * 32 + n8 * 8 + (lane & 3) * 2;
        if (gc >= nout) continue;
        const float bia0 = bias[gc], bia1 = bias[gc + 1];
#pragma unroll
        for (int mt = 0; mt < 4; mt++) {
            const size_t r0 = arow0 + wm * 64 + mt * 16 + (lane >> 2);
            float v[4];
            v[0] = acc[mt][n8][0] + bia0;  v[1] = acc[mt][n8][1] + bia1;
            v[2] = acc[mt][n8][2] + bia0;  v[3] = acc[mt][n8][3] + bia1;
#pragma unroll
            for (int q = 0; q < 4; q++) {
                if (EPI == 1) v[q] = fmaxf(v[q], 0.0f);
                if (EPI == 2) v[q] = 1.0f / (1.0f + __expf(-v[q]));
            }
            if (SPLIT) {
                bf16 h0 = __float2bfloat16_rn(v[0]);
                bf16 h1 = __float2bfloat16_rn(v[1]);
                bf16 h2 = __float2bfloat16_rn(v[2]);
                bf16 h3 = __float2bfloat16_rn(v[3]);
                __nv_bfloat162 hp0, hp1, lp0, lp1;
                hp0.x = h0; hp0.y = h1;  hp1.x = h2; hp1.y = h3;
                lp0.x = __float2bfloat16_rn(v[0] - __bfloat162float(h0));
                lp0.y = __float2bfloat16_rn(v[1] - __bfloat162float(h1));
                lp1.x = __float2bfloat16_rn(v[2] - __bfloat162float(h2));
                lp1.y = __float2bfloat16_rn(v[3] - __bfloat162float(h3));
                *reinterpret_cast<__nv_bfloat162*>(Ch + r0 * ldc + gc)       = hp0;
                *reinterpret_cast<__nv_bfloat162*>(Cl + r0 * ldc + gc)       = lp0;
                *reinterpret_cast<__nv_bfloat162*>(Ch + (r0 + 8) * ldc + gc) = hp1;
                *reinterpret_cast<__nv_bfloat162*>(Cl + (r0 + 8) * ldc + gc) = lp1;
            } else {
                float2 p0, p1;
                p0.x = v[0]; p0.y = v[1];  p1.x = v[2]; p1.y = v[3];
                *reinterpret_cast<float2*>(Cf + r0 * ldc + gc)       = p0;
                *reinterpret_cast<float2*>(Cf + (r0 + 8) * ldc + gc) = p1;
            }
        }
    }
}

// ---------------- x -> hi/lo split (elementwise) ----------------------------
__global__ void split_x(const float4* __restrict__ x,
                        uint2* __restrict__ xh, uint2* __restrict__ xl)
{
    const size_t i = (size_t)blockIdx.x * blockDim.x + threadIdx.x;
    const float4 v = x[i];
    __nv_bfloat162 h01 = __float22bfloat162_rn(make_float2(v.x, v.y));
    __nv_bfloat162 h23 = __float22bfloat162_rn(make_float2(v.z, v.w));
    const float2 f01 = __bfloat1622float2(h01);
    const float2 f23 = __bfloat1622float2(h23);
    __nv_bfloat162 l01 = __float22bfloat162_rn(make_float2(v.x - f01.x, v.y - f01.y));
    __nv_bfloat162 l23 = __float22bfloat162_rn(make_float2(v.z - f23.x, v.w - f23.y));
    uint2 uh, ul;
    uh.x = *reinterpret_cast<uint32_t*>(&h01);
    uh.y = *reinterpret_cast<uint32_t*>(&h23);
    ul.x = *reinterpret_cast<uint32_t*>(&l01);
    ul.y = *reinterpret_cast<uint32_t*>(&l23);
    xh[i] = uh;
    xl[i] = ul;
}

// ---------------- weight prep: transpose [K,N] f32 -> [Np][Kp] bf16 hi/lo --
__global__ void prep_weight(const float* __restrict__ W, int K, int N,
                            bf16* __restrict__ Wh, bf16* __restrict__ Wl,
                            int Kp, int Np)
{
    __shared__ float t[32][33];
    const int k0 = blockIdx.x * 32, n0 = blockIdx.y * 32;
    const int tx = threadIdx.x, ty = threadIdx.y;     // (32, 8)
#pragma unroll
    for (int j = 0; j < 4; j++) {
        const int k = k0 + ty + j * 8, n = n0 + tx;
        t[ty + j * 8][tx] = (k < K && n < N) ? W[(size_t)k * N + n] : 0.0f;
    }
    __syncthreads();
#pragma unroll
    for (int j = 0; j < 4; j++) {
        const int n = n0 + ty + j * 8, k = k0 + tx;
        if (n < Np && k < Kp) {
            const float v = t[tx][ty + j * 8];
            const bf16 h = __float2bfloat16_rn(v);
            Wh[(size_t)n * Kp + k] = h;
            Wl[(size_t)n * Kp + k] = __float2bfloat16_rn(v - __bfloat162float(h));
        }
    }
}

// ------------- per-row heads: rho = tanh(h1@W22+b22), logs = h1@W23+b23 ----
__global__ void rho_logs_kernel(const bf16* __restrict__ h1h,
                                const bf16* __restrict__ h1l,
                                const float* __restrict__ W22,
                                const float* __restrict__ b22,
                                const float* __restrict__ W23,
                                const float* __restrict__ b23,
                                float* __restrict__ rho_out,
                                float* __restrict__ logs_out)
{
    const int row  = blockIdx.x * blockDim.y + threadIdx.y;
    const int lane = threadIdx.x;
    const size_t base = (size_t)row * H_PAD;

    float a = 0.f, b = 0.f;
    for (int i = lane; i < H_DIM; i += 32) {
        const float h = __bfloat162float(h1h[base + i]) + __bfloat162float(h1l[base + i]);
        a = fmaf(h, W22[i], a);
        b = fmaf(h, W23[i], b);
    }
#pragma unroll
    for (int o = 16; o > 0; o >>= 1) {
        a += __shfl_xor_sync(0xffffffffu, a, o);
        b += __shfl_xor_sync(0xffffffffu, b, o);
    }
    if (lane == 0) {
        const float logs = b + b23[0];
        rho_out[row]  = tanhf(a + b22[0]);
        logs_out[row] = logs;
        g_std[row]    = sqrtf(expf(logs));
    }
}

// ------------- z = cumsum(eps * std, axis=1) + mu, warp per row ------------
__global__ __launch_bounds__(256) void scan_kernel(
    const float* __restrict__ eps, const float* __restrict__ mu,
    bf16* __restrict__ zh, bf16* __restrict__ zl)
{
    const int warp = threadIdx.x >> 5, lane = threadIdx.x & 31;
    const int row  = blockIdx.x * 8 + warp;
    const float s  = g_std[row];
    const size_t base = (size_t)row * Z_DIM + lane * 16;

    float v[16];
#pragma unroll
    for (int q = 0; q < 4; q++) {
        const float4 e = *reinterpret_cast<const float4*>(eps + base + q * 4);
        v[q * 4 + 0] = e.x * s;  v[q * 4 + 1] = e.y * s;
        v[q * 4 + 2] = e.z * s;  v[q * 4 + 3] = e.w * s;
    }
#pragma unroll
    for (int q = 1; q < 16; q++) v[q] += v[q - 1];
    float tot = v[15];
#pragma unroll
    for (int o = 1; o < 32; o <<= 1) {
        const float n = __shfl_up_sync(0xffffffffu, tot, o);
        if (lane >= o) tot += n;
    }
    const float off = tot - v[15];        // exclusive prefix for this lane

    __nv_bfloat162 hp[8], lp[8];
#pragma unroll
    for (int q = 0; q < 4; q++) {
        const float4 m = *reinterpret_cast<const float4*>(mu + base + q * 4);
        float w0 = v[q * 4 + 0] + off + m.x;
        float w1 = v[q * 4 + 1] + off + m.y;
        float w2 = v[q * 4 + 2] + off + m.z;
        float w3 = v[q * 4 + 3] + off + m.w;
        bf16 h0 = __float2bfloat16_rn(w0), h1 = __float2bfloat16_rn(w1);
        bf16 h2 = __float2bfloat16_rn(w2), h3 = __float2bfloat16_rn(w3);
        hp[q * 2].x = h0;     hp[q * 2].y = h1;
        hp[q * 2 + 1].x = h2; hp[q * 2 + 1].y = h3;
        lp[q * 2].x = __float2bfloat16_rn(w0 - __bfloat162float(h0));
        lp[q * 2].y = __float2bfloat16_rn(w1 - __bfloat162float(h1));
        lp[q * 2 + 1].x = __float2bfloat16_rn(w2 - __bfloat162float(h2));
        lp[q * 2 + 1].y = __float2bfloat16_rn(w3 - __bfloat162float(h3));
    }
    *reinterpret_cast<uint4*>(zh + base)     = *reinterpret_cast<uint4*>(&hp[0]);
    *reinterpret_cast<uint4*>(zh + base + 8) = *reinterpret_cast<uint4*>(&hp[4]);
    *reinterpret_cast<uint4*>(zl + base)     = *reinterpret_cast<uint4*>(&lp[0]);
    *reinterpret_cast<uint4*>(zl + base + 8) = *reinterpret_cast<uint4*>(&lp[4]);
}

// ---------------------------------------------------------------------------
extern "C" void kernel_launch(void* const* d_in, const int* in_sizes, int n_in,
                              void* d_out, int out_size)
{
    const float* x   = (const float*)d_in[0];
    const float* eps = (const float*)d_in[1];
    const float* W1  = (const float*)d_in[2];
    const float* b1  = (const float*)d_in[3];
    const float* W21 = (const float*)d_in[4];
    const float* b21 = (const float*)d_in[5];
    const float* W22 = (const float*)d_in[6];
    const float* b22 = (const float*)d_in[7];
    const float* W23 = (const float*)d_in[8];
    const float* b23 = (const float*)d_in[9];
    const float* W3  = (const float*)d_in[10];
    const float* b3  = (const float*)d_in[11];
    const float* W4  = (const float*)d_in[12];
    const float* b4  = (const float*)d_in[13];

    float* out       = (float*)d_out;
    float* out_recon = out;                                    // [B, 4096]
    float* out_mu    = out_recon + (size_t)B_ROWS * DATA_DIM;  // [B, 512]
    float* out_rho   = out_mu    + (size_t)B_ROWS * Z_DIM;     // [B, 1]
    float* out_logs  = out_rho   + B_ROWS;                     // [B, 1]

    bf16 *xh, *xl, *h1h, *h1l, *zh, *zl, *h3h, *h3l;
    bf16 *W1h, *W1l, *W21h, *W21l, *W3h, *W3l, *W4h, *W4l;
    cudaGetSymbolAddress((void**)&xh,   g_xh);
    cudaGetSymbolAddress((void**)&xl,   g_xl);
    cudaGetSymbolAddress((void**)&h1h,  g_h1h);
    cudaGetSymbolAddress((void**)&h1l,  g_h1l);
    cudaGetSymbolAddress((void**)&zh,   g_zh);
    cudaGetSymbolAddress((void**)&zl,   g_zl);
    cudaGetSymbolAddress((void**)&h3h,  g_h3h);
    cudaGetSymbolAddress((void**)&h3l,  g_h3l);
    cudaGetSymbolAddress((void**)&W1h,  g_W1h);
    cudaGetSymbolAddress((void**)&W1l,  g_W1l);
    cudaGetSymbolAddress((void**)&W21h, g_W21h);
    cudaGetSymbolAddress((void**)&W21l, g_W21l);
    cudaGetSymbolAddress((void**)&W3h,  g_W3h);
    cudaGetSymbolAddress((void**)&W3l,  g_W3l);
    cudaGetSymbolAddress((void**)&W4h,  g_W4h);
    cudaGetSymbolAddress((void**)&W4l,  g_W4l);

    cudaFuncSetAttribute(gemm_mma<1, 1>, cudaFuncAttributeMaxDynamicSharedMemorySize, SMEM_TOT);
    cudaFuncSetAttribute(gemm_mma<0, 0>, cudaFuncAttributeMaxDynamicSharedMemorySize, SMEM_TOT);
    cudaFuncSetAttribute(gemm_mma<2, 0>, cudaFuncAttributeMaxDynamicSharedMemorySize, SMEM_TOT);

    const dim3 pb(32, 8);

    // idx0: x -> hi/lo
    split_x<<<(B_ROWS * DATA_DIM / 4) / 256, 256>>>(
        (const float4*)x, (uint2*)xh, (uint2*)xl);
    // idx1, idx2: weights needed by gemm1/gemm2
    prep_weight<<<dim3(DATA_DIM / 32, N1_PAD / 32), pb>>>(W1,  DATA_DIM, H_DIM, W1h,  W1l,  DATA_DIM, N1_PAD);
    prep_weight<<<dim3(H_PAD / 32,    Z_DIM / 32),  pb>>>(W21, H_DIM,    Z_DIM, W21h, W21l, H_PAD,    Z_DIM);

    // idx3 (ncu capture slot): h1 = relu(x @ W1 + b1) -> hi/lo
    gemm_mma<1, 1><<<dim3(N1_PAD / 128, B_ROWS / 128), 256, SMEM_TOT>>>(
        xh, xl, DATA_DIM, W1h, W1l, DATA_DIM, b1,
        nullptr, h1h, h1l, H_PAD, H_DIM, DATA_DIM);

    // idx4: rho / logs / std
    rho_logs_kernel<<<B_ROWS / 8, dim3(32, 8)>>>(
        h1h, h1l, W22, b22, W23, b23, out_rho, out_logs);

    // idx5: mu = h1 @ W21 + b21 -> fp32 output
    gemm_mma<0, 0><<<dim3(Z_DIM / 128, B_ROWS / 128), 256, SMEM_TOT>>>(
        h1h, h1l, H_PAD, W21h, W21l, H_PAD, b21,
        out_mu, nullptr, nullptr, Z_DIM, Z_DIM, H_PAD);

    // idx6: z = cumsum(eps*std) + mu -> hi/lo (warp per row)
    scan_kernel<<<B_ROWS / 8, 256>>>(eps, out_mu, zh, zl);

    // idx7: W3 prep, idx8: h3 = relu(z @ W3 + b3) -> hi/lo
    prep_weight<<<dim3(Z_DIM / 32, N1_PAD / 32), pb>>>(W3, Z_DIM, H_DIM, W3h, W3l, Z_DIM, N1_PAD);
    gemm_mma<1, 1><<<dim3(N1_PAD / 128, B_ROWS / 128), 256, SMEM_TOT>>>(
        zh, zl, Z_DIM, W3h, W3l, Z_DIM, b3,
        nullptr, h3h, h3l, H_PAD, H_DIM, Z_DIM);

    // idx9: W4 prep, idx10: recon = sigmoid(h3 @ W4 + b4) -> fp32 output
    prep_weight<<<dim3(H_PAD / 32, DATA_DIM / 32), pb>>>(W4, H_DIM, DATA_DIM, W4h, W4l, H_PAD, DATA_DIM);
    gemm_mma<2, 0><<<dim3(DATA_DIM / 128, B_ROWS / 128), 256, SMEM_TOT>>>(
        h3h, h3l, H_PAD, W4h, W4l, H_PAD, b4,
        out_recon, nullptr, nullptr, DATA_DIM, DATA_DIM, H_PAD);
}

// round 10
// speedup vs baseline: 3.2016x; 1.1480x over previous
#include <cuda_runtime.h>
#include <cuda_bf16.h>
#include <cstdint>
#include <math.h>

#define B_ROWS   16384
#define DATA_DIM 4096
#define Z_DIM    512
#define H_DIM    400
#define H_PAD    448     // H padded to multiple of 32 (K use)
#define N1_PAD   512     // H padded to multiple of 128 (N-tile use)

typedef __nv_bfloat16 bf16;

// ---------------- scratch (allocation-free device globals, zero-init) ------
__device__ alignas(256) bf16 g_xh [B_ROWS * DATA_DIM];
__device__ alignas(256) bf16 g_xl [B_ROWS * DATA_DIM];
__device__ alignas(256) bf16 g_h1h[B_ROWS * H_PAD];    // pad cols stay zero
__device__ alignas(256) bf16 g_h1l[B_ROWS * H_PAD];
__device__ alignas(256) bf16 g_zh [B_ROWS * Z_DIM];
__device__ alignas(256) bf16 g_zl [B_ROWS * Z_DIM];
__device__ alignas(256) bf16 g_h3h[B_ROWS * H_PAD];
__device__ alignas(256) bf16 g_h3l[B_ROWS * H_PAD];
__device__ float g_std[B_ROWS];
// transposed + split weights [Npad][Kpad] bf16 (K-major), zero padded
__device__ alignas(256) bf16 g_W1h [N1_PAD * DATA_DIM], g_W1l [N1_PAD * DATA_DIM];
__device__ alignas(256) bf16 g_W21h[Z_DIM * H_PAD],     g_W21l[Z_DIM * H_PAD];
__device__ alignas(256) bf16 g_W3h [N1_PAD * Z_DIM],    g_W3l [N1_PAD * Z_DIM];
__device__ alignas(256) bf16 g_W4h [DATA_DIM * H_PAD],  g_W4l [DATA_DIM * H_PAD];

// ---------------- PTX helpers ----------------------------------------------
__device__ __forceinline__ uint32_t smem_u32(const void* p) {
    uint32_t a;
    asm("{ .reg .u64 t; cvta.to.shared.u64 t, %1; cvt.u32.u64 %0, t; }"
        : "=r"(a) : "l"(p));
    return a;
}
__device__ __forceinline__ void cp16(uint32_t dst, const void* src) {
    asm volatile("cp.async.cg.shared.global [%0], [%1], 16;"
                 :: "r"(dst), "l"(src) : "memory");
}
__device__ __forceinline__ void cp_commit() {
    asm volatile("cp.async.commit_group;" ::: "memory");
}
template <int N> __device__ __forceinline__ void cp_wait() {
    asm volatile("cp.async.wait_group %0;" :: "n"(N) : "memory");
}
#define LDSM4(R, addr) \
    asm volatile("ldmatrix.sync.aligned.m8n8.x4.shared.b16 {%0,%1,%2,%3}, [%4];" \
                 : "=r"((R)[0]), "=r"((R)[1]), "=r"((R)[2]), "=r"((R)[3])      \
                 : "r"(addr))
#define MMA16816(C, A, B0, B1) \
    asm volatile("mma.sync.aligned.m16n8k16.row.col.f32.bf16.bf16.f32 "        \
                 "{%0,%1,%2,%3}, {%4,%5,%6,%7}, {%8,%9}, {%0,%1,%2,%3};"       \
                 : "+f"((C)[0]), "+f"((C)[1]), "+f"((C)[2]), "+f"((C)[3])      \
                 : "r"((A)[0]), "r"((A)[1]), "r"((A)[2]), "r"((A)[3]),         \
                   "r"(B0), "r"(B1))

// smem stage: 4 matrices [128 rows][32 bf16 + 8 pad] (80 B rows, 16B aligned)
#define ROWB     80
#define MAT_SZ   10240                 // 128*80
#define OFF_AH   0
#define OFF_AL   10240
#define OFF_BH   20480
#define OFF_BL   30720
#define STAGE_SZ 40960
#define SMEM_TOT (2 * STAGE_SZ)       // 81920 -> two CTAs per SM

// ---------------- stage loader: K-chunk 32, cp.async 16B ------------------
__device__ __forceinline__ void ld_stage(
    uint32_t s0, int tid,
    const bf16* __restrict__ Ah, const bf16* __restrict__ Al,
    size_t arow0, int lda,
    const bf16* __restrict__ Bh, const bf16* __restrict__ Bl,
    size_t brow0, int ldb, int k0)
{
#pragma unroll
    for (int j = 0; j < 8; j++) {
        const int idx = tid + j * 256;          // 0..2047
        const int mat = idx >> 9;               // 0:Ah 1:Al 2:Bh 3:Bl
        const int rem = idx & 511;
        const int row = rem >> 2;               // 0..127
        const int ch  = rem & 3;                // 16B chunk (8 bf16)
        const bf16* src;
        if (mat == 0)      src = Ah + (arow0 + row) * (size_t)lda + k0 + ch * 8;
        else if (mat == 1) src = Al + (arow0 + row) * (size_t)lda + k0 + ch * 8;
        else if (mat == 2) src = Bh + (brow0 + row) * (size_t)ldb + k0 + ch * 8;
        else               src = Bl + (brow0 + row) * (size_t)ldb + k0 + ch * 8;
        cp16(s0 + mat * MAT_SZ + row * ROWB + ch * 16, src);
    }
}

// ---------------- per-ks fragment load + 48 MMAs ---------------------------
__device__ __forceinline__ void compute_ks(
    uint32_t st, int ks, int wm, int wn, int lane, float (&acc)[4][4][4])
{
    uint32_t ah[4][4], al[4][4], bh[4][2], bl[4][2];
#pragma unroll
    for (int mt = 0; mt < 4; mt++) {
        const int row = wm * 64 + mt * 16 + (lane & 15);
        const uint32_t aoff = row * ROWB + ks * 32 + ((lane >> 4) << 4);
        LDSM4(ah[mt], st + OFF_AH + aoff);
        LDSM4(al[mt], st + OFF_AL + aoff);
    }
#pragma unroll
    for (int nt = 0; nt < 2; nt++) {
        const int row = wn * 32 + nt * 16 + (lane & 7) + ((lane >> 4) << 3);
        const uint32_t boff = row * ROWB + ks * 32 + ((lane >> 3) & 1) * 16;
        uint32_t r[4];
        LDSM4(r, st + OFF_BH + boff);
        bh[nt * 2][0] = r[0]; bh[nt * 2][1] = r[1];
        bh[nt * 2 + 1][0] = r[2]; bh[nt * 2 + 1][1] = r[3];
        LDSM4(r, st + OFF_BL + boff);
        bl[nt * 2][0] = r[0]; bl[nt * 2][1] = r[1];
        bl[nt * 2 + 1][0] = r[2]; bl[nt * 2 + 1][1] = r[3];
    }
#pragma unroll
    for (int mt = 0; mt < 4; mt++)
#pragma unroll
        for (int n = 0; n < 4; n++) {
            MMA16816(acc[mt][n], ah[mt], bh[n][0], bh[n][1]);
            MMA16816(acc[mt][n], al[mt], bh[n][0], bh[n][1]);
            MMA16816(acc[mt][n], ah[mt], bl[n][0], bl[n][1]);
        }
}

// ---------------- split-bf16 tensor-core GEMM ------------------------------
// C[128*by.., 128*bx..] = epi(A @ B^T + bias)
// A: bf16 hi/lo [M][lda] row-major; B: bf16 hi/lo [Npad][ldb] K-major.
// EPI: 0 none, 1 relu, 2 sigmoid.  SPLIT: 1 -> store hi/lo bf16, 0 -> fp32.
// Mainloop: ONE barrier per chunk; next-chunk cp.async issued mid-chunk
// (between ks=0 and ks=1) so LSU traffic doesn't collide with the LDSM burst
// at chunk start. Safe: writer of buf (i+1)&1 is behind the top-of-chunk-i
// barrier, which orders it after all chunk-(i-1) readers of that buffer.
template <int EPI, int SPLIT>
__global__ __launch_bounds__(256, 2) void gemm_mma(
    const bf16* __restrict__ Ah, const bf16* __restrict__ Al, int lda,
    const bf16* __restrict__ Bh, const bf16* __restrict__ Bl, int ldb,
    const float* __restrict__ bias,
    float* __restrict__ Cf, bf16* __restrict__ Ch, bf16* __restrict__ Cl,
    int ldc, int nout, int K)
{
    extern __shared__ char smem[];
    const uint32_t sb = smem_u32(smem);
    const int tid  = threadIdx.x;
    const int wid  = tid >> 5, lane = tid & 31;
    const int wm   = wid & 1,  wn   = wid >> 1;   // 2 M-warps x 4 N-warps
    const int bx   = blockIdx.x, by = blockIdx.y;
    const size_t arow0 = (size_t)by * 128;
    const size_t brow0 = (size_t)bx * 128;

    float acc[4][4][4];
#pragma unroll
    for (int a = 0; a < 4; a++)
#pragma unroll
        for (int b = 0; b < 4; b++)
#pragma unroll
            for (int c = 0; c < 4; c++) acc[a][b][c] = 0.0f;

    const int NC = K >> 5;                        // 32-wide K chunks
    ld_stage(sb, tid, Ah, Al, arow0, lda, Bh, Bl, brow0, ldb, 0);
    cp_commit();

    for (int i = 0; i < NC; i++) {
        cp_wait<0>();
        __syncthreads();                          // single barrier per chunk

        const uint32_t st = sb + (i & 1) * STAGE_SZ;
        compute_ks(st, 0, wm, wn, lane, acc);

        if (i + 1 < NC) {                         // mid-chunk prefetch
            ld_stage(sb + ((i + 1) & 1) * STAGE_SZ, tid,
                     Ah, Al, arow0, lda, Bh, Bl, brow0, ldb, (i + 1) << 5);
            cp_commit();
        }

        compute_ks(st, 1, wm, wn, lane, acc);
    }

    // ---- epilogue: bias + activation, direct register stores ----
#pragma unroll
    for (int n8 = 0; n8 < 4; n8++) {
        const int gc = bx * 128 + wn * 32 + n8 * 8 + (lane & 3) * 2;
        if (gc >= nout) continue;
        const float bia0 = bias[gc], bia1 = bias[gc + 1];
#pragma unroll
        for (int mt = 0; mt < 4; mt++) {
            const size_t r0 = arow0 + wm * 64 + mt * 16 + (lane >> 2);
            float v[4];
            v[0] = acc[mt][n8][0] + bia0;  v[1] = acc[mt][n8][1] + bia1;
            v[2] = acc[mt][n8][2] + bia0;  v[3] = acc[mt][n8][3] + bia1;
#pragma unroll
            for (int q = 0; q < 4; q++) {
                if (EPI == 1) v[q] = fmaxf(v[q], 0.0f);
                if (EPI == 2) v[q] = 1.0f / (1.0f + __expf(-v[q]));
            }
            if (SPLIT) {
                bf16 h0 = __float2bfloat16_rn(v[0]);
                bf16 h1 = __float2bfloat16_rn(v[1]);
                bf16 h2 = __float2bfloat16_rn(v[2]);
                bf16 h3 = __float2bfloat16_rn(v[3]);
                __nv_bfloat162 hp0, hp1, lp0, lp1;
                hp0.x = h0; hp0.y = h1;  hp1.x = h2; hp1.y = h3;
                lp0.x = __float2bfloat16_rn(v[0] - __bfloat162float(h0));
                lp0.y = __float2bfloat16_rn(v[1] - __bfloat162float(h1));
                lp1.x = __float2bfloat16_rn(v[2] - __bfloat162float(h2));
                lp1.y = __float2bfloat16_rn(v[3] - __bfloat162float(h3));
                *reinterpret_cast<__nv_bfloat162*>(Ch + r0 * ldc + gc)       = hp0;
                *reinterpret_cast<__nv_bfloat162*>(Cl + r0 * ldc + gc)       = lp0;
                *reinterpret_cast<__nv_bfloat162*>(Ch + (r0 + 8) * ldc + gc) = hp1;
                *reinterpret_cast<__nv_bfloat162*>(Cl + (r0 + 8) * ldc + gc) = lp1;
            } else {
                float2 p0, p1;
                p0.x = v[0]; p0.y = v[1];  p1.x = v[2]; p1.y = v[3];
                *reinterpret_cast<float2*>(Cf + r0 * ldc + gc)       = p0;
                *reinterpret_cast<float2*>(Cf + (r0 + 8) * ldc + gc) = p1;
            }
        }
    }
}

// ---------------- x -> hi/lo split (elementwise) ----------------------------
__global__ void split_x(const float4* __restrict__ x,
                        uint2* __restrict__ xh, uint2* __restrict__ xl)
{
    const size_t i = (size_t)blockIdx.x * blockDim.x + threadIdx.x;
    const float4 v = x[i];
    __nv_bfloat162 h01 = __float22bfloat162_rn(make_float2(v.x, v.y));
    __nv_bfloat162 h23 = __float22bfloat162_rn(make_float2(v.z, v.w));
    const float2 f01 = __bfloat1622float2(h01);
    const float2 f23 = __bfloat1622float2(h23);
    __nv_bfloat162 l01 = __float22bfloat162_rn(make_float2(v.x - f01.x, v.y - f01.y));
    __nv_bfloat162 l23 = __float22bfloat162_rn(make_float2(v.z - f23.x, v.w - f23.y));
    uint2 uh, ul;
    uh.x = *reinterpret_cast<uint32_t*>(&h01);
    uh.y = *reinterpret_cast<uint32_t*>(&h23);
    ul.x = *reinterpret_cast<uint32_t*>(&l01);
    ul.y = *reinterpret_cast<uint32_t*>(&l23);
    xh[i] = uh;
    xl[i] = ul;
}

// ---------------- weight prep: transpose [K,N] f32 -> [Np][Kp] bf16 hi/lo --
__global__ void prep_weight(const float* __restrict__ W, int K, int N,
                            bf16* __restrict__ Wh, bf16* __restrict__ Wl,
                            int Kp, int Np)
{
    __shared__ float t[32][33];
    const int k0 = blockIdx.x * 32, n0 = blockIdx.y * 32;
    const int tx = threadIdx.x, ty = threadIdx.y;     // (32, 8)
#pragma unroll
    for (int j = 0; j < 4; j++) {
        const int k = k0 + ty + j * 8, n = n0 + tx;
        t[ty + j * 8][tx] = (k < K && n < N) ? W[(size_t)k * N + n] : 0.0f;
    }
    __syncthreads();
#pragma unroll
    for (int j = 0; j < 4; j++) {
        const int n = n0 + ty + j * 8, k = k0 + tx;
        if (n < Np && k < Kp) {
            const float v = t[tx][ty + j * 8];
            const bf16 h = __float2bfloat16_rn(v);
            Wh[(size_t)n * Kp + k] = h;
            Wl[(size_t)n * Kp + k] = __float2bfloat16_rn(v - __bfloat162float(h));
        }
    }
}

// ------------- per-row heads: rho = tanh(h1@W22+b22), logs = h1@W23+b23 ----
__global__ void rho_logs_kernel(const bf16* __restrict__ h1h,
                                const bf16* __restrict__ h1l,
                                const float* __restrict__ W22,
                                const float* __restrict__ b22,
                                const float* __restrict__ W23,
                                const float* __restrict__ b23,
                                float* __restrict__ rho_out,
                                float* __restrict__ logs_out)
{
    const int row  = blockIdx.x * blockDim.y + threadIdx.y;
    const int lane = threadIdx.x;
    const size_t base = (size_t)row * H_PAD;

    float a = 0.f, b = 0.f;
    for (int i = lane; i < H_DIM; i += 32) {
        const float h = __bfloat162float(h1h[base + i]) + __bfloat162float(h1l[base + i]);
        a = fmaf(h, W22[i], a);
        b = fmaf(h, W23[i], b);
    }
#pragma unroll
    for (int o = 16; o > 0; o >>= 1) {
        a += __shfl_xor_sync(0xffffffffu, a, o);
        b += __shfl_xor_sync(0xffffffffu, b, o);
    }
    if (lane == 0) {
        const float logs = b + b23[0];
        rho_out[row]  = tanhf(a + b22[0]);
        logs_out[row] = logs;
        g_std[row]    = sqrtf(expf(logs));
    }
}

// ------------- z = cumsum(eps * std, axis=1) + mu, warp per row ------------
__global__ __launch_bounds__(256) void scan_kernel(
    const float* __restrict__ eps, const float* __restrict__ mu,
    bf16* __restrict__ zh, bf16* __restrict__ zl)
{
    const int warp = threadIdx.x >> 5, lane = threadIdx.x & 31;
    const int row  = blockIdx.x * 8 + warp;
    const float s  = g_std[row];
    const size_t base = (size_t)row * Z_DIM + lane * 16;

    float v[16];
#pragma unroll
    for (int q = 0; q < 4; q++) {
        const float4 e = *reinterpret_cast<const float4*>(eps + base + q * 4);
        v[q * 4 + 0] = e.x * s;  v[q * 4 + 1] = e.y * s;
        v[q * 4 + 2] = e.z * s;  v[q * 4 + 3] = e.w * s;
    }
#pragma unroll
    for (int q = 1; q < 16; q++) v[q] += v[q - 1];
    float tot = v[15];
#pragma unroll
    for (int o = 1; o < 32; o <<= 1) {
        const float n = __shfl_up_sync(0xffffffffu, tot, o);
        if (lane >= o) tot += n;
    }
    const float off = tot - v[15];        // exclusive prefix for this lane

    __nv_bfloat162 hp[8], lp[8];
#pragma unroll
    for (int q = 0; q < 4; q++) {
        const float4 m = *reinterpret_cast<const float4*>(mu + base + q * 4);
        float w0 = v[q * 4 + 0] + off + m.x;
        float w1 = v[q * 4 + 1] + off + m.y;
        float w2 = v[q * 4 + 2] + off + m.z;
        float w3 = v[q * 4 + 3] + off + m.w;
        bf16 h0 = __float2bfloat16_rn(w0), h1 = __float2bfloat16_rn(w1);
        bf16 h2 = __float2bfloat16_rn(w2), h3 = __float2bfloat16_rn(w3);
        hp[q * 2].x = h0;     hp[q * 2].y = h1;
        hp[q * 2 + 1].x = h2; hp[q * 2 + 1].y = h3;
        lp[q * 2].x = __float2bfloat16_rn(w0 - __bfloat162float(h0));
        lp[q * 2].y = __float2bfloat16_rn(w1 - __bfloat162float(h1));
        lp[q * 2 + 1].x = __float2bfloat16_rn(w2 - __bfloat162float(h2));
        lp[q * 2 + 1].y = __float2bfloat16_rn(w3 - __bfloat162float(h3));
    }
    *reinterpret_cast<uint4*>(zh + base)     = *reinterpret_cast<uint4*>(&hp[0]);
    *reinterpret_cast<uint4*>(zh + base + 8) = *reinterpret_cast<uint4*>(&hp[4]);
    *reinterpret_cast<uint4*>(zl + base)     = *reinterpret_cast<uint4*>(&lp[0]);
    *reinterpret_cast<uint4*>(zl + base + 8) = *reinterpret_cast<uint4*>(&lp[4]);
}

// ---------------------------------------------------------------------------
extern "C" void kernel_launch(void* const* d_in, const int* in_sizes, int n_in,
                              void* d_out, int out_size)
{
    const float* x   = (const float*)d_in[0];
    const float* eps = (const float*)d_in[1];
    const float* W1  = (const float*)d_in[2];
    const float* b1  = (const float*)d_in[3];
    const float* W21 = (const float*)d_in[4];
    const float* b21 = (const float*)d_in[5];
    const float* W22 = (const float*)d_in[6];
    const float* b22 = (const float*)d_in[7];
    const float* W23 = (const float*)d_in[8];
    const float* b23 = (const float*)d_in[9];
    const float* W3  = (const float*)d_in[10];
    const float* b3  = (const float*)d_in[11];
    const float* W4  = (const float*)d_in[12];
    const float* b4  = (const float*)d_in[13];

    float* out       = (float*)d_out;
    float* out_recon = out;                                    // [B, 4096]
    float* out_mu    = out_recon + (size_t)B_ROWS * DATA_DIM;  // [B, 512]
    float* out_rho   = out_mu    + (size_t)B_ROWS * Z_DIM;     // [B, 1]
    float* out_logs  = out_rho   + B_ROWS;                     // [B, 1]

    bf16 *xh, *xl, *h1h, *h1l, *zh, *zl, *h3h, *h3l;
    bf16 *W1h, *W1l, *W21h, *W21l, *W3h, *W3l, *W4h, *W4l;
    cudaGetSymbolAddress((void**)&xh,   g_xh);
    cudaGetSymbolAddress((void**)&xl,   g_xl);
    cudaGetSymbolAddress((void**)&h1h,  g_h1h);
    cudaGetSymbolAddress((void**)&h1l,  g_h1l);
    cudaGetSymbolAddress((void**)&zh,   g_zh);
    cudaGetSymbolAddress((void**)&zl,   g_zl);
    cudaGetSymbolAddress((void**)&h3h,  g_h3h);
    cudaGetSymbolAddress((void**)&h3l,  g_h3l);
    cudaGetSymbolAddress((void**)&W1h,  g_W1h);
    cudaGetSymbolAddress((void**)&W1l,  g_W1l);
    cudaGetSymbolAddress((void**)&W21h, g_W21h);
    cudaGetSymbolAddress((void**)&W21l, g_W21l);
    cudaGetSymbolAddress((void**)&W3h,  g_W3h);
    cudaGetSymbolAddress((void**)&W3l,  g_W3l);
    cudaGetSymbolAddress((void**)&W4h,  g_W4h);
    cudaGetSymbolAddress((void**)&W4l,  g_W4l);

    cudaFuncSetAttribute(gemm_mma<1, 1>, cudaFuncAttributeMaxDynamicSharedMemorySize, SMEM_TOT);
    cudaFuncSetAttribute(gemm_mma<0, 0>, cudaFuncAttributeMaxDynamicSharedMemorySize, SMEM_TOT);
    cudaFuncSetAttribute(gemm_mma<2, 0>, cudaFuncAttributeMaxDynamicSharedMemorySize, SMEM_TOT);

    const dim3 pb(32, 8);

    // idx0: x -> hi/lo
    split_x<<<(B_ROWS * DATA_DIM / 4) / 256, 256>>>(
        (const float4*)x, (uint2*)xh, (uint2*)xl);
    // idx1, idx2: weights needed by gemm1/gemm2
    prep_weight<<<dim3(DATA_DIM / 32, N1_PAD / 32), pb>>>(W1,  DATA_DIM, H_DIM, W1h,  W1l,  DATA_DIM, N1_PAD);
    prep_weight<<<dim3(H_PAD / 32,    Z_DIM / 32),  pb>>>(W21, H_DIM,    Z_DIM, W21h, W21l, H_PAD,    Z_DIM);

    // idx3 (ncu capture slot): h1 = relu(x @ W1 + b1) -> hi/lo
    gemm_mma<1, 1><<<dim3(N1_PAD / 128, B_ROWS / 128), 256, SMEM_TOT>>>(
        xh, xl, DATA_DIM, W1h, W1l, DATA_DIM, b1,
        nullptr, h1h, h1l, H_PAD, H_DIM, DATA_DIM);

    // idx4: rho / logs / std
    rho_logs_kernel<<<B_ROWS / 8, dim3(32, 8)>>>(
        h1h, h1l, W22, b22, W23, b23, out_rho, out_logs);

    // idx5: mu = h1 @ W21 + b21 -> fp32 output
    gemm_mma<0, 0><<<dim3(Z_DIM / 128, B_ROWS / 128), 256, SMEM_TOT>>>(
        h1h, h1l, H_PAD, W21h, W21l, H_PAD, b21,
        out_mu, nullptr, nullptr, Z_DIM, Z_DIM, H_PAD);

    // idx6: z = cumsum(eps*std) + mu -> hi/lo (warp per row)
    scan_kernel<<<B_ROWS / 8, 256>>>(eps, out_mu, zh, zl);

    // idx7: W3 prep, idx8: h3 = relu(z @ W3 + b3) -> hi/lo
    prep_weight<<<dim3(Z_DIM / 32, N1_PAD / 32), pb>>>(W3, Z_DIM, H_DIM, W3h, W3l, Z_DIM, N1_PAD);
    gemm_mma<1, 1><<<dim3(N1_PAD / 128, B_ROWS / 128), 256, SMEM_TOT>>>(
        zh, zl, Z_DIM, W3h, W3l, Z_DIM, b3,
        nullptr, h3h, h3l, H_PAD, H_DIM, Z_DIM);

    // idx9: W4 prep, idx10: recon = sigmoid(h3 @ W4 + b4) -> fp32 output
    prep_weight<<<dim3(H_PAD / 32, DATA_DIM / 32), pb>>>(W4, H_DIM, DATA_DIM, W4h, W4l, H_PAD, DATA_DIM);
    gemm_mma<2, 0><<<dim3(DATA_DIM / 128, B_ROWS / 128), 256, SMEM_TOT>>>(
        h3h, h3l, H_PAD, W4h, W4l, H_PAD, b4,
        out_recon, nullptr, nullptr, DATA_DIM, DATA_DIM, H_PAD);
}

// round 11
// speedup vs baseline: 3.2456x; 1.0138x over previous
#include <cuda_runtime.h>
#include <cuda_bf16.h>
#include <cstdint>
#include <math.h>

#define B_ROWS   16384
#define DATA_DIM 4096
#define Z_DIM    512
#define H_DIM    400
#define H_PAD    416     // H padded to multiple of 32 (K-chunk); cols 400-415 stay zero
#define N1_PAD   512     // H padded to multiple of 128 (N-tile grid)

typedef __nv_bfloat16 bf16;

// ---------------- scratch (allocation-free device globals, zero-init) ------
__device__ alignas(256) bf16 g_xh [B_ROWS * DATA_DIM];
__device__ alignas(256) bf16 g_xl [B_ROWS * DATA_DIM];
__device__ alignas(256) bf16 g_h1h[B_ROWS * H_PAD];    // pad cols stay zero
__device__ alignas(256) bf16 g_h1l[B_ROWS * H_PAD];
__device__ alignas(256) bf16 g_zh [B_ROWS * Z_DIM];
__device__ alignas(256) bf16 g_zl [B_ROWS * Z_DIM];
__device__ alignas(256) bf16 g_h3h[B_ROWS * H_PAD];
__device__ alignas(256) bf16 g_h3l[B_ROWS * H_PAD];
__device__ float g_std[B_ROWS];
// transposed + split weights [Npad][Kpad] bf16 (K-major), zero padded
__device__ alignas(256) bf16 g_W1h [N1_PAD * DATA_DIM], g_W1l [N1_PAD * DATA_DIM];
__device__ alignas(256) bf16 g_W21h[Z_DIM * H_PAD],     g_W21l[Z_DIM * H_PAD];
__device__ alignas(256) bf16 g_W3h [N1_PAD * Z_DIM],    g_W3l [N1_PAD * Z_DIM];
__device__ alignas(256) bf16 g_W4h [DATA_DIM * H_PAD],  g_W4l [DATA_DIM * H_PAD];

// ---------------- PTX helpers ----------------------------------------------
__device__ __forceinline__ uint32_t smem_u32(const void* p) {
    uint32_t a;
    asm("{ .reg .u64 t; cvta.to.shared.u64 t, %1; cvt.u32.u64 %0, t; }"
        : "=r"(a) : "l"(p));
    return a;
}
__device__ __forceinline__ void cp16(uint32_t dst, const void* src) {
    asm volatile("cp.async.cg.shared.global [%0], [%1], 16;"
                 :: "r"(dst), "l"(src) : "memory");
}
__device__ __forceinline__ void cp_commit() {
    asm volatile("cp.async.commit_group;" ::: "memory");
}
template <int N> __device__ __forceinline__ void cp_wait() {
    asm volatile("cp.async.wait_group %0;" :: "n"(N) : "memory");
}
#define LDSM4(R, addr) \
    asm volatile("ldmatrix.sync.aligned.m8n8.x4.shared.b16 {%0,%1,%2,%3}, [%4];" \
                 : "=r"((R)[0]), "=r"((R)[1]), "=r"((R)[2]), "=r"((R)[3])      \
                 : "r"(addr))
#define MMA16816(C, A, B0, B1) \
    asm volatile("mma.sync.aligned.m16n8k16.row.col.f32.bf16.bf16.f32 "        \
                 "{%0,%1,%2,%3}, {%4,%5,%6,%7}, {%8,%9}, {%0,%1,%2,%3};"       \
                 : "+f"((C)[0]), "+f"((C)[1]), "+f"((C)[2]), "+f"((C)[3])      \
                 : "r"((A)[0]), "r"((A)[1]), "r"((A)[2]), "r"((A)[3]),         \
                   "r"(B0), "r"(B1))

// smem stage: 4 matrices [128 rows][32 bf16 + 8 pad] (80 B rows, 16B aligned)
#define ROWB     80
#define MAT_SZ   10240                 // 128*80
#define OFF_AH   0
#define OFF_AL   10240
#define OFF_BH   20480
#define OFF_BL   30720
#define STAGE_SZ 40960
#define SMEM_TOT (2 * STAGE_SZ)       // 81920 -> two CTAs per SM

// ---------------- stage loader: K-chunk 32, cp.async 16B ------------------
__device__ __forceinline__ void ld_stage(
    uint32_t s0, int tid,
    const bf16* __restrict__ Ah, const bf16* __restrict__ Al,
    size_t arow0, int lda,
    const bf16* __restrict__ Bh, const bf16* __restrict__ Bl,
    size_t brow0, int ldb, int k0)
{
#pragma unroll
    for (int j = 0; j < 8; j++) {
        const int idx = tid + j * 256;          // 0..2047
        const int mat = idx >> 9;               // 0:Ah 1:Al 2:Bh 3:Bl
        const int rem = idx & 511;
        const int row = rem >> 2;               // 0..127
        const int ch  = rem & 3;                // 16B chunk (8 bf16)
        const bf16* src;
        if (mat == 0)      src = Ah + (arow0 + row) * (size_t)lda + k0 + ch * 8;
        else if (mat == 1) src = Al + (arow0 + row) * (size_t)lda + k0 + ch * 8;
        else if (mat == 2) src = Bh + (brow0 + row) * (size_t)ldb + k0 + ch * 8;
        else               src = Bl + (brow0 + row) * (size_t)ldb + k0 + ch * 8;
        cp16(s0 + mat * MAT_SZ + row * ROWB + ch * 16, src);
    }
}

// ---------------- per-ks fragment load + 48 MMAs ---------------------------
__device__ __forceinline__ void compute_ks(
    uint32_t st, int ks, int wm, int wn, int lane, float (&acc)[4][4][4])
{
    uint32_t ah[4][4], al[4][4], bh[4][2], bl[4][2];
#pragma unroll
    for (int mt = 0; mt < 4; mt++) {
        const int row = wm * 64 + mt * 16 + (lane & 15);
        const uint32_t aoff = row * ROWB + ks * 32 + ((lane >> 4) << 4);
        LDSM4(ah[mt], st + OFF_AH + aoff);
        LDSM4(al[mt], st + OFF_AL + aoff);
    }
#pragma unroll
    for (int nt = 0; nt < 2; nt++) {
        const int row = wn * 32 + nt * 16 + (lane & 7) + ((lane >> 4) << 3);
        const uint32_t boff = row * ROWB + ks * 32 + ((lane >> 3) & 1) * 16;
        uint32_t r[4];
        LDSM4(r, st + OFF_BH + boff);
        bh[nt * 2][0] = r[0]; bh[nt * 2][1] = r[1];
        bh[nt * 2 + 1][0] = r[2]; bh[nt * 2 + 1][1] = r[3];
        LDSM4(r, st + OFF_BL + boff);
        bl[nt * 2][0] = r[0]; bl[nt * 2][1] = r[1];
        bl[nt * 2 + 1][0] = r[2]; bl[nt * 2 + 1][1] = r[3];
    }
#pragma unroll
    for (int mt = 0; mt < 4; mt++)
#pragma unroll
        for (int n = 0; n < 4; n++) {
            MMA16816(acc[mt][n], ah[mt], bh[n][0], bh[n][1]);
            MMA16816(acc[mt][n], al[mt], bh[n][0], bh[n][1]);
            MMA16816(acc[mt][n], ah[mt], bl[n][0], bl[n][1]);
        }
}

// ---------------- split-bf16 tensor-core GEMM ------------------------------
// C[128*by.., 128*bx..] = epi(A @ B^T + bias)
// A: bf16 hi/lo [M][lda] row-major; B: bf16 hi/lo [Npad][ldb] K-major.
// EPI: 0 none, 1 relu, 2 sigmoid.  SPLIT: 1 -> store hi/lo bf16, 0 -> fp32.
// Warps whose 32-col N-tile lies entirely beyond nout skip all LDSM/MMA work
// (block-wide loads + barriers still executed), halving per-SMSP tensor work
// on the mostly-padding bx tile.
template <int EPI, int SPLIT>
__global__ __launch_bounds__(256, 2) void gemm_mma(
    const bf16* __restrict__ Ah, const bf16* __restrict__ Al, int lda,
    const bf16* __restrict__ Bh, const bf16* __restrict__ Bl, int ldb,
    const float* __restrict__ bias,
    float* __restrict__ Cf, bf16* __restrict__ Ch, bf16* __restrict__ Cl,
    int ldc, int nout, int K)
{
    extern __shared__ char smem[];
    const uint32_t sb = smem_u32(smem);
    const int tid  = threadIdx.x;
    const int wid  = tid >> 5, lane = tid & 31;
    const int wm   = wid & 1,  wn   = wid >> 1;   // 2 M-warps x 4 N-warps
    const int bx   = blockIdx.x, by = blockIdx.y;
    const size_t arow0 = (size_t)by * 128;
    const size_t brow0 = (size_t)bx * 128;
    const bool active = (bx * 128 + wn * 32) < nout;   // warp-uniform

    float acc[4][4][4];
#pragma unroll
    for (int a = 0; a < 4; a++)
#pragma unroll
        for (int b = 0; b < 4; b++)
#pragma unroll
            for (int c = 0; c < 4; c++) acc[a][b][c] = 0.0f;

    const int NC = K >> 5;                        // 32-wide K chunks
    ld_stage(sb, tid, Ah, Al, arow0, lda, Bh, Bl, brow0, ldb, 0);
    cp_commit();

    for (int i = 0; i < NC; i++) {
        cp_wait<0>();
        __syncthreads();                          // single barrier per chunk

        const uint32_t st = sb + (i & 1) * STAGE_SZ;
        if (active) compute_ks(st, 0, wm, wn, lane, acc);

        if (i + 1 < NC) {                         // mid-chunk prefetch
            ld_stage(sb + ((i + 1) & 1) * STAGE_SZ, tid,
                     Ah, Al, arow0, lda, Bh, Bl, brow0, ldb, (i + 1) << 5);
            cp_commit();
        }

        if (active) compute_ks(st, 1, wm, wn, lane, acc);
    }

    // ---- epilogue: bias + activation, direct register stores ----
    if (active) {
#pragma unroll
    for (int n8 = 0; n8 < 4; n8++) {
        const int gc = bx * 128 + wn * 32 + n8 * 8 + (lane & 3) * 2;
        if (gc >= nout) continue;
        const float bia0 = bias[gc], bia1 = bias[gc + 1];
#pragma unroll
        for (int mt = 0; mt < 4; mt++) {
            const size_t r0 = arow0 + wm * 64 + mt * 16 + (lane >> 2);
            float v[4];
            v[0] = acc[mt][n8][0] + bia0;  v[1] = acc[mt][n8][1] + bia1;
            v[2] = acc[mt][n8][2] + bia0;  v[3] = acc[mt][n8][3] + bia1;
#pragma unroll
            for (int q = 0; q < 4; q++) {
                if (EPI == 1) v[q] = fmaxf(v[q], 0.0f);
                if (EPI == 2) v[q] = 1.0f / (1.0f + __expf(-v[q]));
            }
            if (SPLIT) {
                bf16 h0 = __float2bfloat16_rn(v[0]);
                bf16 h1 = __float2bfloat16_rn(v[1]);
                bf16 h2 = __float2bfloat16_rn(v[2]);
                bf16 h3 = __float2bfloat16_rn(v[3]);
                __nv_bfloat162 hp0, hp1, lp0, lp1;
                hp0.x = h0; hp0.y = h1;  hp1.x = h2; hp1.y = h3;
                lp0.x = __float2bfloat16_rn(v[0] - __bfloat162float(h0));
                lp0.y = __float2bfloat16_rn(v[1] - __bfloat162float(h1));
                lp1.x = __float2bfloat16_rn(v[2] - __bfloat162float(h2));
                lp1.y = __float2bfloat16_rn(v[3] - __bfloat162float(h3));
                *reinterpret_cast<__nv_bfloat162*>(Ch + r0 * ldc + gc)       = hp0;
                *reinterpret_cast<__nv_bfloat162*>(Cl + r0 * ldc + gc)       = lp0;
                *reinterpret_cast<__nv_bfloat162*>(Ch + (r0 + 8) * ldc + gc) = hp1;
                *reinterpret_cast<__nv_bfloat162*>(Cl + (r0 + 8) * ldc + gc) = lp1;
            } else {
                float2 p0, p1;
                p0.x = v[0]; p0.y = v[1];  p1.x = v[2]; p1.y = v[3];
                *reinterpret_cast<float2*>(Cf + r0 * ldc + gc)       = p0;
                *reinterpret_cast<float2*>(Cf + (r0 + 8) * ldc + gc) = p1;
            }
        }
    }
    }
}

// ---------------- x -> hi/lo split (elementwise) ----------------------------
__global__ void split_x(const float4* __restrict__ x,
                        uint2* __restrict__ xh, uint2* __restrict__ xl)
{
    const size_t i = (size_t)blockIdx.x * blockDim.x + threadIdx.x;
    const float4 v = x[i];
    __nv_bfloat162 h01 = __float22bfloat162_rn(make_float2(v.x, v.y));
    __nv_bfloat162 h23 = __float22bfloat162_rn(make_float2(v.z, v.w));
    const float2 f01 = __bfloat1622float2(h01);
    const float2 f23 = __bfloat1622float2(h23);
    __nv_bfloat162 l01 = __float22bfloat162_rn(make_float2(v.x - f01.x, v.y - f01.y));
    __nv_bfloat162 l23 = __float22bfloat162_rn(make_float2(v.z - f23.x, v.w - f23.y));
    uint2 uh, ul;
    uh.x = *reinterpret_cast<uint32_t*>(&h01);
    uh.y = *reinterpret_cast<uint32_t*>(&h23);
    ul.x = *reinterpret_cast<uint32_t*>(&l01);
    ul.y = *reinterpret_cast<uint32_t*>(&l23);
    xh[i] = uh;
    xl[i] = ul;
}

// ---------------- weight prep: transpose [K,N] f32 -> [Np][Kp] bf16 hi/lo --
__global__ void prep_weight(const float* __restrict__ W, int K, int N,
                            bf16* __restrict__ Wh, bf16* __restrict__ Wl,
                            int Kp, int Np)
{
    __shared__ float t[32][33];
    const int k0 = blockIdx.x * 32, n0 = blockIdx.y * 32;
    const int tx = threadIdx.x, ty = threadIdx.y;     // (32, 8)
#pragma unroll
    for (int j = 0; j < 4; j++) {
        const int k = k0 + ty + j * 8, n = n0 + tx;
        t[ty + j * 8][tx] = (k < K && n < N) ? W[(size_t)k * N + n] : 0.0f;
    }
    __syncthreads();
#pragma unroll
    for (int j = 0; j < 4; j++) {
        const int n = n0 + ty + j * 8, k = k0 + tx;
        if (n < Np && k < Kp) {
            const float v = t[tx][ty + j * 8];
            const bf16 h = __float2bfloat16_rn(v);
            Wh[(size_t)n * Kp + k] = h;
            Wl[(size_t)n * Kp + k] = __float2bfloat16_rn(v - __bfloat162float(h));
        }
    }
}

// ------------- per-row heads: rho = tanh(h1@W22+b22), logs = h1@W23+b23 ----
__global__ void rho_logs_kernel(const bf16* __restrict__ h1h,
                                const bf16* __restrict__ h1l,
                                const float* __restrict__ W22,
                                const float* __restrict__ b22,
                                const float* __restrict__ W23,
                                const float* __restrict__ b23,
                                float* __restrict__ rho_out,
                                float* __restrict__ logs_out)
{
    const int row  = blockIdx.x * blockDim.y + threadIdx.y;
    const int lane = threadIdx.x;
    const size_t base = (size_t)row * H_PAD;

    float a = 0.f, b = 0.f;
    for (int i = lane; i < H_DIM; i += 32) {
        const float h = __bfloat162float(h1h[base + i]) + __bfloat162float(h1l[base + i]);
        a = fmaf(h, W22[i], a);
        b = fmaf(h, W23[i], b);
    }
#pragma unroll
    for (int o = 16; o > 0; o >>= 1) {
        a += __shfl_xor_sync(0xffffffffu, a, o);
        b += __shfl_xor_sync(0xffffffffu, b, o);
    }
    if (lane == 0) {
        const float logs = b + b23[0];
        rho_out[row]  = tanhf(a + b22[0]);
        logs_out[row] = logs;
        g_std[row]    = sqrtf(expf(logs));
    }
}

// ------------- z = cumsum(eps * std, axis=1) + mu, warp per row ------------
__global__ __launch_bounds__(256) void scan_kernel(
    const float* __restrict__ eps, const float* __restrict__ mu,
    bf16* __restrict__ zh, bf16* __restrict__ zl)
{
    const int warp = threadIdx.x >> 5, lane = threadIdx.x & 31;
    const int row  = blockIdx.x * 8 + warp;
    const float s  = g_std[row];
    const size_t base = (size_t)row * Z_DIM + lane * 16;

    float v[16];
#pragma unroll
    for (int q = 0; q < 4; q++) {
        const float4 e = *reinterpret_cast<const float4*>(eps + base + q * 4);
        v[q * 4 + 0] = e.x * s;  v[q * 4 + 1] = e.y * s;
        v[q * 4 + 2] = e.z * s;  v[q * 4 + 3] = e.w * s;
    }
#pragma unroll
    for (int q = 1; q < 16; q++) v[q] += v[q - 1];
    float tot = v[15];
#pragma unroll
    for (int o = 1; o < 32; o <<= 1) {
        const float n = __shfl_up_sync(0xffffffffu, tot, o);
        if (lane >= o) tot += n;
    }
    const float off = tot - v[15];        // exclusive prefix for this lane

    __nv_bfloat162 hp[8], lp[8];
#pragma unroll
    for (int q = 0; q < 4; q++) {
        const float4 m = *reinterpret_cast<const float4*>(mu + base + q * 4);
        float w0 = v[q * 4 + 0] + off + m.x;
        float w1 = v[q * 4 + 1] + off + m.y;
        float w2 = v[q * 4 + 2] + off + m.z;
        float w3 = v[q * 4 + 3] + off + m.w;
        bf16 h0 = __float2bfloat16_rn(w0), h1 = __float2bfloat16_rn(w1);
        bf16 h2 = __float2bfloat16_rn(w2), h3 = __float2bfloat16_rn(w3);
        hp[q * 2].x = h0;     hp[q * 2].y = h1;
        hp[q * 2 + 1].x = h2; hp[q * 2 + 1].y = h3;
        lp[q * 2].x = __float2bfloat16_rn(w0 - __bfloat162float(h0));
        lp[q * 2].y = __float2bfloat16_rn(w1 - __bfloat162float(h1));
        lp[q * 2 + 1].x = __float2bfloat16_rn(w2 - __bfloat162float(h2));
        lp[q * 2 + 1].y = __float2bfloat16_rn(w3 - __bfloat162float(h3));
    }
    *reinterpret_cast<uint4*>(zh + base)     = *reinterpret_cast<uint4*>(&hp[0]);
    *reinterpret_cast<uint4*>(zh + base + 8) = *reinterpret_cast<uint4*>(&hp[4]);
    *reinterpret_cast<uint4*>(zl + base)     = *reinterpret_cast<uint4*>(&lp[0]);
    *reinterpret_cast<uint4*>(zl + base + 8) = *reinterpret_cast<uint4*>(&lp[4]);
}

// ---------------------------------------------------------------------------
extern "C" void kernel_launch(void* const* d_in, const int* in_sizes, int n_in,
                              void* d_out, int out_size)
{
    const float* x   = (const float*)d_in[0];
    const float* eps = (const float*)d_in[1];
    const float* W1  = (const float*)d_in[2];
    const float* b1  = (const float*)d_in[3];
    const float* W21 = (const float*)d_in[4];
    const float* b21 = (const float*)d_in[5];
    const float* W22 = (const float*)d_in[6];
    const float* b22 = (const float*)d_in[7];
    const float* W23 = (const float*)d_in[8];
    const float* b23 = (const float*)d_in[9];
    const float* W3  = (const float*)d_in[10];
    const float* b3  = (const float*)d_in[11];
    const float* W4  = (const float*)d_in[12];
    const float* b4  = (const float*)d_in[13];

    float* out       = (float*)d_out;
    float* out_recon = out;                                    // [B, 4096]
    float* out_mu    = out_recon + (size_t)B_ROWS * DATA_DIM;  // [B, 512]
    float* out_rho   = out_mu    + (size_t)B_ROWS * Z_DIM;     // [B, 1]
    float* out_logs  = out_rho   + B_ROWS;                     // [B, 1]

    bf16 *xh, *xl, *h1h, *h1l, *zh, *zl, *h3h, *h3l;
    bf16 *W1h, *W1l, *W21h, *W21l, *W3h, *W3l, *W4h, *W4l;
    cudaGetSymbolAddress((void**)&xh,   g_xh);
    cudaGetSymbolAddress((void**)&xl,   g_xl);
    cudaGetSymbolAddress((void**)&h1h,  g_h1h);
    cudaGetSymbolAddress((void**)&h1l,  g_h1l);
    cudaGetSymbolAddress((void**)&zh,   g_zh);
    cudaGetSymbolAddress((void**)&zl,   g_zl);
    cudaGetSymbolAddress((void**)&h3h,  g_h3h);
    cudaGetSymbolAddress((void**)&h3l,  g_h3l);
    cudaGetSymbolAddress((void**)&W1h,  g_W1h);
    cudaGetSymbolAddress((void**)&W1l,  g_W1l);
    cudaGetSymbolAddress((void**)&W21h, g_W21h);
    cudaGetSymbolAddress((void**)&W21l, g_W21l);
    cudaGetSymbolAddress((void**)&W3h,  g_W3h);
    cudaGetSymbolAddress((void**)&W3l,  g_W3l);
    cudaGetSymbolAddress((void**)&W4h,  g_W4h);
    cudaGetSymbolAddress((void**)&W4l,  g_W4l);

    cudaFuncSetAttribute(gemm_mma<1, 1>, cudaFuncAttributeMaxDynamicSharedMemorySize, SMEM_TOT);
    cudaFuncSetAttribute(gemm_mma<0, 0>, cudaFuncAttributeMaxDynamicSharedMemorySize, SMEM_TOT);
    cudaFuncSetAttribute(gemm_mma<2, 0>, cudaFuncAttributeMaxDynamicSharedMemorySize, SMEM_TOT);

    const dim3 pb(32, 8);

    // idx0: x -> hi/lo
    split_x<<<(B_ROWS * DATA_DIM / 4) / 256, 256>>>(
        (const float4*)x, (uint2*)xh, (uint2*)xl);
    // idx1, idx2: weights needed by gemm1/gemm2
    prep_weight<<<dim3(DATA_DIM / 32, N1_PAD / 32), pb>>>(W1,  DATA_DIM, H_DIM, W1h,  W1l,  DATA_DIM, N1_PAD);
    prep_weight<<<dim3(H_PAD / 32,    Z_DIM / 32),  pb>>>(W21, H_DIM,    Z_DIM, W21h, W21l, H_PAD,    Z_DIM);

    // idx3 (ncu capture slot): h1 = relu(x @ W1 + b1) -> hi/lo
    gemm_mma<1, 1><<<dim3(N1_PAD / 128, B_ROWS / 128), 256, SMEM_TOT>>>(
        xh, xl, DATA_DIM, W1h, W1l, DATA_DIM, b1,
        nullptr, h1h, h1l, H_PAD, H_DIM, DATA_DIM);

    // idx4: rho / logs / std
    rho_logs_kernel<<<B_ROWS / 8, dim3(32, 8)>>>(
        h1h, h1l, W22, b22, W23, b23, out_rho, out_logs);

    // idx5: mu = h1 @ W21 + b21 -> fp32 output
    gemm_mma<0, 0><<<dim3(Z_DIM / 128, B_ROWS / 128), 256, SMEM_TOT>>>(
        h1h, h1l, H_PAD, W21h, W21l, H_PAD, b21,
        out_mu, nullptr, nullptr, Z_DIM, Z_DIM, H_PAD);

    // idx6: z = cumsum(eps*std) + mu -> hi/lo (warp per row)
    scan_kernel<<<B_ROWS / 8, 256>>>(eps, out_mu, zh, zl);

    // idx7: W3 prep, idx8: h3 = relu(z @ W3 + b3) -> hi/lo
    prep_weight<<<dim3(Z_DIM / 32, N1_PAD / 32), pb>>>(W3, Z_DIM, H_DIM, W3h, W3l, Z_DIM, N1_PAD);
    gemm_mma<1, 1><<<dim3(N1_PAD / 128, B_ROWS / 128), 256, SMEM_TOT>>>(
        zh, zl, Z_DIM, W3h, W3l, Z_DIM, b3,
        nullptr, h3h, h3l, H_PAD, H_DIM, Z_DIM);

    // idx9: W4 prep, idx10: recon = sigmoid(h3 @ W4 + b4) -> fp32 output
    prep_weight<<<dim3(H_PAD / 32, DATA_DIM / 32), pb>>>(W4, H_DIM, DATA_DIM, W4h, W4l, H_PAD, DATA_DIM);
    gemm_mma<2, 0><<<dim3(DATA_DIM / 128, B_ROWS / 128), 256, SMEM_TOT>>>(
        h3h, h3l, H_PAD, W4h, W4l, H_PAD, b4,
        out_recon, nullptr, nullptr, DATA_DIM, DATA_DIM, H_PAD);
}

// round 12
// speedup vs baseline: 4.5984x; 1.4168x over previous
#include <cuda_runtime.h>
#include <cuda_fp16.h>
#include <cstdint>
#include <math.h>

#define B_ROWS   16384
#define DATA_DIM 4096
#define Z_DIM    512
#define H_DIM    400
#define H_PAD    416     // H padded to multiple of 32 (K-chunk); cols 400-415 stay zero
#define N1_PAD   512     // H padded to multiple of 128 (N-tile grid)

typedef __half f16;

// ---------------- scratch (allocation-free device globals, zero-init) ------
__device__ alignas(256) f16 g_xq [B_ROWS * DATA_DIM];
__device__ alignas(256) f16 g_h1q[B_ROWS * H_PAD];     // pad cols stay zero
__device__ alignas(256) f16 g_zq [B_ROWS * Z_DIM];
__device__ alignas(256) f16 g_h3q[B_ROWS * H_PAD];
__device__ float g_std[B_ROWS];
// transposed + split weights [Npad][Kpad] f16 hi/lo (K-major), zero padded
__device__ alignas(256) f16 g_W1h [N1_PAD * DATA_DIM], g_W1l [N1_PAD * DATA_DIM];
__device__ alignas(256) f16 g_W21h[Z_DIM * H_PAD],     g_W21l[Z_DIM * H_PAD];
__device__ alignas(256) f16 g_W3h [N1_PAD * Z_DIM],    g_W3l [N1_PAD * Z_DIM];
__device__ alignas(256) f16 g_W4h [DATA_DIM * H_PAD],  g_W4l [DATA_DIM * H_PAD];

// ---------------- PTX helpers ----------------------------------------------
__device__ __forceinline__ uint32_t smem_u32(const void* p) {
    uint32_t a;
    asm("{ .reg .u64 t; cvta.to.shared.u64 t, %1; cvt.u32.u64 %0, t; }"
        : "=r"(a) : "l"(p));
    return a;
}
__device__ __forceinline__ void cp16(uint32_t dst, const void* src) {
    asm volatile("cp.async.cg.shared.global [%0], [%1], 16;"
                 :: "r"(dst), "l"(src) : "memory");
}
__device__ __forceinline__ void cp_commit() {
    asm volatile("cp.async.commit_group;" ::: "memory");
}
template <int N> __device__ __forceinline__ void cp_wait() {
    asm volatile("cp.async.wait_group %0;" :: "n"(N) : "memory");
}
#define LDSM4(R, addr) \
    asm volatile("ldmatrix.sync.aligned.m8n8.x4.shared.b16 {%0,%1,%2,%3}, [%4];" \
                 : "=r"((R)[0]), "=r"((R)[1]), "=r"((R)[2]), "=r"((R)[3])      \
                 : "r"(addr))
#define MMA16816(C, A, B0, B1) \
    asm volatile("mma.sync.aligned.m16n8k16.row.col.f32.f16.f16.f32 "          \
                 "{%0,%1,%2,%3}, {%4,%5,%6,%7}, {%8,%9}, {%0,%1,%2,%3};"       \
                 : "+f"((C)[0]), "+f"((C)[1]), "+f"((C)[2]), "+f"((C)[3])      \
                 : "r"((A)[0]), "r"((A)[1]), "r"((A)[2]), "r"((A)[3]),         \
                   "r"(B0), "r"(B1))

// smem stage: 3 matrices [128 rows][32 f16 + 8 pad] (80 B rows, 16B aligned)
#define ROWB     80
#define MAT_SZ   10240                 // 128*80
#define OFF_A    0
#define OFF_BH   10240
#define OFF_BL   20480
#define STAGE_SZ 30720
#define SMEM_TOT (2 * STAGE_SZ)       // 61440 -> two CTAs per SM

// ---------------- stage loader: K-chunk 32, cp.async 16B ------------------
__device__ __forceinline__ void ld_stage(
    uint32_t s0, int tid,
    const f16* __restrict__ Aq, size_t arow0, int lda,
    const f16* __restrict__ Bh, const f16* __restrict__ Bl,
    size_t brow0, int ldb, int k0)
{
#pragma unroll
    for (int j = 0; j < 6; j++) {
        const int idx = tid + j * 256;          // 0..1535
        const int mat = idx >> 9;               // 0:A 1:Bh 2:Bl
        const int rem = idx & 511;
        const int row = rem >> 2;               // 0..127
        const int ch  = rem & 3;                // 16B chunk (8 f16)
        const f16* src;
        if (mat == 0)      src = Aq + (arow0 + row) * (size_t)lda + k0 + ch * 8;
        else if (mat == 1) src = Bh + (brow0 + row) * (size_t)ldb + k0 + ch * 8;
        else               src = Bl + (brow0 + row) * (size_t)ldb + k0 + ch * 8;
        cp16(s0 + mat * MAT_SZ + row * ROWB + ch * 16, src);
    }
}

// ---------------- per-ks fragment load + 32 MMAs ---------------------------
__device__ __forceinline__ void compute_ks(
    uint32_t st, int ks, int wm, int wn, int lane, float (&acc)[4][4][4])
{
    uint32_t a[4][4], bh[4][2], bl[4][2];
#pragma unroll
    for (int mt = 0; mt < 4; mt++) {
        const int row = wm * 64 + mt * 16 + (lane & 15);
        const uint32_t aoff = row * ROWB + ks * 32 + ((lane >> 4) << 4);
        LDSM4(a[mt], st + OFF_A + aoff);
    }
#pragma unroll
    for (int nt = 0; nt < 2; nt++) {
        const int row = wn * 32 + nt * 16 + (lane & 7) + ((lane >> 4) << 3);
        const uint32_t boff = row * ROWB + ks * 32 + ((lane >> 3) & 1) * 16;
        uint32_t r[4];
        LDSM4(r, st + OFF_BH + boff);
        bh[nt * 2][0] = r[0]; bh[nt * 2][1] = r[1];
        bh[nt * 2 + 1][0] = r[2]; bh[nt * 2 + 1][1] = r[3];
        LDSM4(r, st + OFF_BL + boff);
        bl[nt * 2][0] = r[0]; bl[nt * 2][1] = r[1];
        bl[nt * 2 + 1][0] = r[2]; bl[nt * 2 + 1][1] = r[3];
    }
#pragma unroll
    for (int mt = 0; mt < 4; mt++)
#pragma unroll
        for (int n = 0; n < 4; n++) {
            MMA16816(acc[mt][n], a[mt], bh[n][0], bh[n][1]);
            MMA16816(acc[mt][n], a[mt], bl[n][0], bl[n][1]);
        }
}

// ---------------- fp16-activation / split-fp16-weight GEMM -----------------
// C[128*by.., 128*bx..] = epi(A @ (Bh+Bl)^T + bias)
// A: f16 [M][lda] row-major; B: f16 hi/lo [Npad][ldb] K-major.
// EPI: 0 none, 1 relu, 2 sigmoid.  HOUT: 1 -> store f16, 0 -> fp32.
template <int EPI, int HOUT>
__global__ __launch_bounds__(256, 2) void gemm_mma(
    const f16* __restrict__ Aq, int lda,
    const f16* __restrict__ Bh, const f16* __restrict__ Bl, int ldb,
    const float* __restrict__ bias,
    float* __restrict__ Cf, f16* __restrict__ Ch,
    int ldc, int nout, int K)
{
    extern __shared__ char smem[];
    const uint32_t sb = smem_u32(smem);
    const int tid  = threadIdx.x;
    const int wid  = tid >> 5, lane = tid & 31;
    const int wm   = wid & 1,  wn   = wid >> 1;   // 2 M-warps x 4 N-warps
    const int bx   = blockIdx.x, by = blockIdx.y;
    const size_t arow0 = (size_t)by * 128;
    const size_t brow0 = (size_t)bx * 128;
    const bool active = (bx * 128 + wn * 32) < nout;   // warp-uniform

    float acc[4][4][4];
#pragma unroll
    for (int a = 0; a < 4; a++)
#pragma unroll
        for (int b = 0; b < 4; b++)
#pragma unroll
            for (int c = 0; c < 4; c++) acc[a][b][c] = 0.0f;

    const int NC = K >> 5;                        // 32-wide K chunks
    ld_stage(sb, tid, Aq, arow0, lda, Bh, Bl, brow0, ldb, 0);
    cp_commit();

    for (int i = 0; i < NC; i++) {
        cp_wait<0>();
        __syncthreads();                          // single barrier per chunk

        const uint32_t st = sb + (i & 1) * STAGE_SZ;
        if (active) compute_ks(st, 0, wm, wn, lane, acc);

        if (i + 1 < NC) {                         // mid-chunk prefetch
            ld_stage(sb + ((i + 1) & 1) * STAGE_SZ, tid,
                     Aq, arow0, lda, Bh, Bl, brow0, ldb, (i + 1) << 5);
            cp_commit();
        }

        if (active) compute_ks(st, 1, wm, wn, lane, acc);
    }

    // ---- epilogue: bias + activation, direct register stores ----
    if (active) {
#pragma unroll
    for (int n8 = 0; n8 < 4; n8++) {
        const int gc = bx * 128 + wn * 32 + n8 * 8 + (lane & 3) * 2;
        if (gc >= nout) continue;
        const float bia0 = bias[gc], bia1 = bias[gc + 1];
#pragma unroll
        for (int mt = 0; mt < 4; mt++) {
            const size_t r0 = arow0 + wm * 64 + mt * 16 + (lane >> 2);
            float v[4];
            v[0] = acc[mt][n8][0] + bia0;  v[1] = acc[mt][n8][1] + bia1;
            v[2] = acc[mt][n8][2] + bia0;  v[3] = acc[mt][n8][3] + bia1;
#pragma unroll
            for (int q = 0; q < 4; q++) {
                if (EPI == 1) v[q] = fmaxf(v[q], 0.0f);
                if (EPI == 2) v[q] = 1.0f / (1.0f + __expf(-v[q]));
            }
            if (HOUT) {
                __half2 p0 = __floats2half2_rn(v[0], v[1]);
                __half2 p1 = __floats2half2_rn(v[2], v[3]);
                *reinterpret_cast<__half2*>(Ch + r0 * ldc + gc)       = p0;
                *reinterpret_cast<__half2*>(Ch + (r0 + 8) * ldc + gc) = p1;
            } else {
                float2 p0, p1;
                p0.x = v[0]; p0.y = v[1];  p1.x = v[2]; p1.y = v[3];
                *reinterpret_cast<float2*>(Cf + r0 * ldc + gc)       = p0;
                *reinterpret_cast<float2*>(Cf + (r0 + 8) * ldc + gc) = p1;
            }
        }
    }
    }
}

// ---------------- x -> fp16 (elementwise) -----------------------------------
__global__ void cvt_x(const float4* __restrict__ x, uint4* __restrict__ xq)
{
    const size_t i = (size_t)blockIdx.x * blockDim.x + threadIdx.x;
    const float4 a = x[i * 2];
    const float4 b = x[i * 2 + 1];
    __half2 h0 = __floats2half2_rn(a.x, a.y);
    __half2 h1 = __floats2half2_rn(a.z, a.w);
    __half2 h2 = __floats2half2_rn(b.x, b.y);
    __half2 h3 = __floats2half2_rn(b.z, b.w);
    uint4 u;
    u.x = *reinterpret_cast<uint32_t*>(&h0);
    u.y = *reinterpret_cast<uint32_t*>(&h1);
    u.z = *reinterpret_cast<uint32_t*>(&h2);
    u.w = *reinterpret_cast<uint32_t*>(&h3);
    xq[i] = u;
}

// ---------------- weight prep: transpose [K,N] f32 -> [Np][Kp] f16 hi/lo ---
__global__ void prep_weight(const float* __restrict__ W, int K, int N,
                            f16* __restrict__ Wh, f16* __restrict__ Wl,
                            int Kp, int Np)
{
    __shared__ float t[32][33];
    const int k0 = blockIdx.x * 32, n0 = blockIdx.y * 32;
    const int tx = threadIdx.x, ty = threadIdx.y;     // (32, 8)
#pragma unroll
    for (int j = 0; j < 4; j++) {
        const int k = k0 + ty + j * 8, n = n0 + tx;
        t[ty + j * 8][tx] = (k < K && n < N) ? W[(size_t)k * N + n] : 0.0f;
    }
    __syncthreads();
#pragma unroll
    for (int j = 0; j < 4; j++) {
        const int n = n0 + ty + j * 8, k = k0 + tx;
        if (n < Np && k < Kp) {
            const float v = t[tx][ty + j * 8];
            const f16 h = __float2half_rn(v);
            Wh[(size_t)n * Kp + k] = h;
            Wl[(size_t)n * Kp + k] = __float2half_rn(v - __half2float(h));
        }
    }
}

// ------------- per-row heads: rho = tanh(h1@W22+b22), logs = h1@W23+b23 ----
__global__ void rho_logs_kernel(const f16* __restrict__ h1q,
                                const float* __restrict__ W22,
                                const float* __restrict__ b22,
                                const float* __restrict__ W23,
                                const float* __restrict__ b23,
                                float* __restrict__ rho_out,
                                float* __restrict__ logs_out)
{
    const int row  = blockIdx.x * blockDim.y + threadIdx.y;
    const int lane = threadIdx.x;
    const size_t base = (size_t)row * H_PAD;

    float a = 0.f, b = 0.f;
    for (int i = lane; i < H_DIM; i += 32) {
        const float h = __half2float(h1q[base + i]);
        a = fmaf(h, W22[i], a);
        b = fmaf(h, W23[i], b);
    }
#pragma unroll
    for (int o = 16; o > 0; o >>= 1) {
        a += __shfl_xor_sync(0xffffffffu, a, o);
        b += __shfl_xor_sync(0xffffffffu, b, o);
    }
    if (lane == 0) {
        const float logs = b + b23[0];
        rho_out[row]  = tanhf(a + b22[0]);
        logs_out[row] = logs;
        g_std[row]    = sqrtf(expf(logs));
    }
}

// ------------- z = cumsum(eps * std, axis=1) + mu, warp per row ------------
__global__ __launch_bounds__(256) void scan_kernel(
    const float* __restrict__ eps, const float* __restrict__ mu,
    f16* __restrict__ zq)
{
    const int warp = threadIdx.x >> 5, lane = threadIdx.x & 31;
    const int row  = blockIdx.x * 8 + warp;
    const float s  = g_std[row];
    const size_t base = (size_t)row * Z_DIM + lane * 16;

    float v[16];
#pragma unroll
    for (int q = 0; q < 4; q++) {
        const float4 e = *reinterpret_cast<const float4*>(eps + base + q * 4);
        v[q * 4 + 0] = e.x * s;  v[q * 4 + 1] = e.y * s;
        v[q * 4 + 2] = e.z * s;  v[q * 4 + 3] = e.w * s;
    }
#pragma unroll
    for (int q = 1; q < 16; q++) v[q] += v[q - 1];
    float tot = v[15];
#pragma unroll
    for (int o = 1; o < 32; o <<= 1) {
        const float n = __shfl_up_sync(0xffffffffu, tot, o);
        if (lane >= o) tot += n;
    }
    const float off = tot - v[15];        // exclusive prefix for this lane

    __half2 hp[8];
#pragma unroll
    for (int q = 0; q < 4; q++) {
        const float4 m = *reinterpret_cast<const float4*>(mu + base + q * 4);
        hp[q * 2]     = __floats2half2_rn(v[q * 4 + 0] + off + m.x,
                                          v[q * 4 + 1] + off + m.y);
        hp[q * 2 + 1] = __floats2half2_rn(v[q * 4 + 2] + off + m.z,
                                          v[q * 4 + 3] + off + m.w);
    }
    *reinterpret_cast<uint4*>(zq + base)     = *reinterpret_cast<uint4*>(&hp[0]);
    *reinterpret_cast<uint4*>(zq + base + 8) = *reinterpret_cast<uint4*>(&hp[4]);
}

// ---------------------------------------------------------------------------
extern "C" void kernel_launch(void* const* d_in, const int* in_sizes, int n_in,
                              void* d_out, int out_size)
{
    const float* x   = (const float*)d_in[0];
    const float* eps = (const float*)d_in[1];
    const float* W1  = (const float*)d_in[2];
    const float* b1  = (const float*)d_in[3];
    const float* W21 = (const float*)d_in[4];
    const float* b21 = (const float*)d_in[5];
    const float* W22 = (const float*)d_in[6];
    const float* b22 = (const float*)d_in[7];
    const float* W23 = (const float*)d_in[8];
    const float* b23 = (const float*)d_in[9];
    const float* W3  = (const float*)d_in[10];
    const float* b3  = (const float*)d_in[11];
    const float* W4  = (const float*)d_in[12];
    const float* b4  = (const float*)d_in[13];

    float* out       = (float*)d_out;
    float* out_recon = out;                                    // [B, 4096]
    float* out_mu    = out_recon + (size_t)B_ROWS * DATA_DIM;  // [B, 512]
    float* out_rho   = out_mu    + (size_t)B_ROWS * Z_DIM;     // [B, 1]
    float* out_logs  = out_rho   + B_ROWS;                     // [B, 1]

    f16 *xq, *h1q, *zq, *h3q;
    f16 *W1h, *W1l, *W21h, *W21l, *W3h, *W3l, *W4h, *W4l;
    cudaGetSymbolAddress((void**)&xq,   g_xq);
    cudaGetSymbolAddress((void**)&h1q,  g_h1q);
    cudaGetSymbolAddress((void**)&zq,   g_zq);
    cudaGetSymbolAddress((void**)&h3q,  g_h3q);
    cudaGetSymbolAddress((void**)&W1h,  g_W1h);
    cudaGetSymbolAddress((void**)&W1l,  g_W1l);
    cudaGetSymbolAddress((void**)&W21h, g_W21h);
    cudaGetSymbolAddress((void**)&W21l, g_W21l);
    cudaGetSymbolAddress((void**)&W3h,  g_W3h);
    cudaGetSymbolAddress((void**)&W3l,  g_W3l);
    cudaGetSymbolAddress((void**)&W4h,  g_W4h);
    cudaGetSymbolAddress((void**)&W4l,  g_W4l);

    cudaFuncSetAttribute(gemm_mma<1, 1>, cudaFuncAttributeMaxDynamicSharedMemorySize, SMEM_TOT);
    cudaFuncSetAttribute(gemm_mma<0, 0>, cudaFuncAttributeMaxDynamicSharedMemorySize, SMEM_TOT);
    cudaFuncSetAttribute(gemm_mma<2, 0>, cudaFuncAttributeMaxDynamicSharedMemorySize, SMEM_TOT);

    const dim3 pb(32, 8);

    // idx0: x -> fp16
    cvt_x<<<(B_ROWS * DATA_DIM / 8) / 256, 256>>>(
        (const float4*)x, (uint4*)xq);
    // idx1, idx2: weights needed by gemm1/gemm2
    prep_weight<<<dim3(DATA_DIM / 32, N1_PAD / 32), pb>>>(W1,  DATA_DIM, H_DIM, W1h,  W1l,  DATA_DIM, N1_PAD);
    prep_weight<<<dim3(H_PAD / 32,    Z_DIM / 32),  pb>>>(W21, H_DIM,    Z_DIM, W21h, W21l, H_PAD,    Z_DIM);

    // idx3 (ncu capture slot): h1 = relu(x @ W1 + b1) -> f16
    gemm_mma<1, 1><<<dim3(N1_PAD / 128, B_ROWS / 128), 256, SMEM_TOT>>>(
        xq, DATA_DIM, W1h, W1l, DATA_DIM, b1,
        nullptr, h1q, H_PAD, H_DIM, DATA_DIM);

    // idx4: rho / logs / std
    rho_logs_kernel<<<B_ROWS / 8, dim3(32, 8)>>>(
        h1q, W22, b22, W23, b23, out_rho, out_logs);

    // idx5: mu = h1 @ W21 + b21 -> fp32 output
    gemm_mma<0, 0><<<dim3(Z_DIM / 128, B_ROWS / 128), 256, SMEM_TOT>>>(
        h1q, H_PAD, W21h, W21l, H_PAD, b21,
        out_mu, nullptr, Z_DIM, Z_DIM, H_PAD);

    // idx6: z = cumsum(eps*std) + mu -> f16 (warp per row)
    scan_kernel<<<B_ROWS / 8, 256>>>(eps, out_mu, zq);

    // idx7: W3 prep, idx8: h3 = relu(z @ W3 + b3) -> f16
    prep_weight<<<dim3(Z_DIM / 32, N1_PAD / 32), pb>>>(W3, Z_DIM, H_DIM, W3h, W3l, Z_DIM, N1_PAD);
    gemm_mma<1, 1><<<dim3(N1_PAD / 128, B_ROWS / 128), 256, SMEM_TOT>>>(
        zq, Z_DIM, W3h, W3l, Z_DIM, b3,
        nullptr, h3q, H_PAD, H_DIM, Z_DIM);

    // idx9: W4 prep, idx10: recon = sigmoid(h3 @ W4 + b4) -> fp32 output
    prep_weight<<<dim3(H_PAD / 32, DATA_DIM / 32), pb>>>(W4, H_DIM, DATA_DIM, W4h, W4l, H_PAD, DATA_DIM);
    gemm_mma<2, 0><<<dim3(DATA_DIM / 128, B_ROWS / 128), 256, SMEM_TOT>>>(
        h3q, H_PAD, W4h, W4l, H_PAD, b4,
        out_recon, nullptr, DATA_DIM, DATA_DIM, H_PAD);
}